// round 3
// baseline (speedup 1.0000x reference)
#include <cuda_runtime.h>
#include <math.h>

#define N_NODES 100000
#define D 202
#define D_PAD 204            // padded row for 16B-aligned v4 atomics
#define E_TYPES 6
#define M_EDGES 200000
#define N_POS 512
#define DE (D * E_TYPES)     // 1212
#define N_EDGES_TOTAL (E_TYPES * M_EDGES)  // 1,200,000

// ---------------- device scratch (no allocations allowed) ----------------
__device__ float g_prop[(size_t)N_NODES * DE];     // 485 MB: node_states @ W_transform + b
__device__ float g_gate[N_POS * D];                // 2*sigmoid(pos_emb @ W_pos + b_pos)
__device__ float g_acc[(size_t)N_NODES * D_PAD];   // padded accumulator (16B-aligned rows)
__device__ float g_cnt[N_NODES];                   // per-target edge count

// ---------------- zero accumulator + counts ----------------
__global__ void zero_kernel() {
    size_t i = (size_t)blockIdx.x * blockDim.x + threadIdx.x;
    size_t total_acc = (size_t)N_NODES * D_PAD;
    if (i < total_acc) g_acc[i] = 0.0f;
    else if (i < total_acc + N_NODES) g_cnt[i - total_acc] = 0.0f;
}

// ---------------- position gating table: 512 x 202 ----------------
// emb[p, i]      = sin(p * 10000^(-i/100))   i in [0,100)
// emb[p, 100+i]  = cos(p * 10000^(-i/100))
// emb[p, 200..201] = 0
// gate = 2*sigmoid(emb @ W_pos + b_pos)
__global__ void gating_kernel(const float* __restrict__ W_pos,
                              const float* __restrict__ b_pos) {
    __shared__ float emb[D];
    int p = blockIdx.x;
    int t = threadIdx.x;
    if (t < 100) {
        float inv = powf(10000.0f, -(float)t / 100.0f);
        float s = (float)p * inv;
        emb[t]       = sinf(s);
        emb[100 + t] = cosf(s);
    }
    if (t == 100) { emb[200] = 0.0f; emb[201] = 0.0f; }
    __syncthreads();
    for (int c = t; c < D; c += blockDim.x) {
        float acc = b_pos[c];
        #pragma unroll 4
        for (int k = 0; k < 200; k++)        // rows 200,201 of emb are zero
            acc += emb[k] * W_pos[k * D + c];
        g_gate[p * D + c] = 2.0f / (1.0f + expf(-acc));
    }
}

// ---------------- prop GEMM: C[100000,1212] = A[100000,202] @ W[202,1212] + b ----------------
#define BM 64
#define BN 64
#define BK 16
#define TM 4
#define TN 4

__global__ __launch_bounds__(256)
void gemm_prop_kernel(const float* __restrict__ A,
                      const float* __restrict__ W,
                      const float* __restrict__ bias) {
    __shared__ __align__(16) float As[BK][BM];   // transposed A tile
    __shared__ __align__(16) float Bs[BK][BN];

    int bm = blockIdx.y * BM;
    int bn = blockIdx.x * BN;
    int tid = threadIdx.x;           // 0..255
    int tx = tid & 15;               // 0..15 -> N
    int ty = tid >> 4;               // 0..15 -> M

    float acc[TM][TN];
    #pragma unroll
    for (int i = 0; i < TM; i++)
        #pragma unroll
        for (int j = 0; j < TN; j++) acc[i][j] = 0.0f;

    for (int kk = 0; kk < D; kk += BK) {
        // load A tile: BM x BK, store transposed As[k][m]
        #pragma unroll
        for (int i = tid; i < BM * BK; i += 256) {
            int m = i >> 4;          // i / BK
            int k = i & 15;          // i % BK
            int gm = bm + m, gk = kk + k;
            As[k][m] = (gm < N_NODES && gk < D) ? A[(size_t)gm * D + gk] : 0.0f;
        }
        // load W tile: BK x BN
        #pragma unroll
        for (int i = tid; i < BK * BN; i += 256) {
            int k = i >> 6;          // i / BN
            int n = i & 63;          // i % BN
            int gk = kk + k, gn = bn + n;
            Bs[k][n] = (gk < D && gn < DE) ? W[(size_t)gk * DE + gn] : 0.0f;
        }
        __syncthreads();

        #pragma unroll
        for (int k = 0; k < BK; k++) {
            float a[TM], b[TN];
            #pragma unroll
            for (int i = 0; i < TM; i++) a[i] = As[k][ty * TM + i];
            #pragma unroll
            for (int j = 0; j < TN; j++) b[j] = Bs[k][tx * TN + j];
            #pragma unroll
            for (int i = 0; i < TM; i++)
                #pragma unroll
                for (int j = 0; j < TN; j++)
                    acc[i][j] += a[i] * b[j];
        }
        __syncthreads();
    }

    #pragma unroll
    for (int i = 0; i < TM; i++) {
        int gm = bm + ty * TM + i;
        if (gm >= N_NODES) continue;
        #pragma unroll
        for (int j = 0; j < TN; j++) {
            int gn = bn + tx * TN + j;
            if (gn < DE)
                g_prop[(size_t)gm * DE + gn] = acc[i][j] + bias[gn];
        }
    }
}

// ---------------- edge scatter: warp per edge, vectorized red.global ----------------
// msgs[e,m,:] = prop[src, e, :] * gate[pos, :]  ->  atomically added to acc[tgt, :]
__global__ __launch_bounds__(256)
void scatter_kernel(const int* __restrict__ edges,
                    const int* __restrict__ pos_lists) {
    int w = (int)((blockIdx.x * (size_t)blockDim.x + threadIdx.x) >> 5);
    int lane = threadIdx.x & 31;
    if (w >= N_EDGES_TOTAL) return;

    int e = w / M_EDGES;
    int m = w - e * M_EDGES;
    int eidx = e * M_EDGES + m;
    int src = edges[2 * eidx + 0];
    int tgt = edges[2 * eidx + 1];
    int p   = pos_lists[eidx];

    // prop row base: (src*1212 + e*202) floats -> byte offset divisible by 8 always
    const float2* pr2 = (const float2*)(g_prop + (size_t)src * DE + (size_t)e * D);
    const float2* gt2 = (const float2*)(g_gate + (size_t)p * D);
    float* op = g_acc + (size_t)tgt * D_PAD;   // byte offset tgt*816 -> 16B aligned

    // 50 groups of 4 floats (elements 0..199), red.v4 at 16B-aligned addresses
    for (int j4 = lane; j4 < 50; j4 += 32) {
        float2 a0 = pr2[2 * j4];
        float2 a1 = pr2[2 * j4 + 1];
        float2 g0 = gt2[2 * j4];
        float2 g1 = gt2[2 * j4 + 1];
        float v0 = a0.x * g0.x;
        float v1 = a0.y * g0.y;
        float v2 = a1.x * g1.x;
        float v3 = a1.y * g1.y;
        asm volatile("red.global.add.v4.f32 [%0], {%1, %2, %3, %4};"
                     :: "l"(op + 4 * j4), "f"(v0), "f"(v1), "f"(v2), "f"(v3)
                     : "memory");
    }
    // tail: elements 200,201 (8B-aligned)
    if (lane == 31) {
        float2 a = pr2[100];
        float2 g = gt2[100];
        float v0 = a.x * g.x;
        float v1 = a.y * g.y;
        asm volatile("red.global.add.v2.f32 [%0], {%1, %2};"
                     :: "l"(op + 200), "f"(v0), "f"(v1)
                     : "memory");
    }
    if (lane == 0) {
        atomicAdd(&g_cnt[tgt], 1.0f);
    }
}

// ---------------- normalize + write output ----------------
__global__ void divide_kernel(float* __restrict__ out) {
    int i = blockIdx.x * blockDim.x + threadIdx.x;
    if (i >= N_NODES * D) return;
    int n = i / D;
    int c = i - n * D;
    float cnt = g_cnt[n];
    float div = (cnt == 0.0f ? 1.0f : cnt) + 1e-8f;
    out[i] = g_acc[(size_t)n * D_PAD + c] / div;
}

// ---------------- launch ----------------
extern "C" void kernel_launch(void* const* d_in, const int* in_sizes, int n_in,
                              void* d_out, int out_size) {
    const float* node_states = (const float*)d_in[0];
    const int*   edges       = (const int*)  d_in[1];
    const int*   pos_lists   = (const int*)  d_in[2];
    const float* W_transform = (const float*)d_in[3];
    const float* b_transform = (const float*)d_in[4];
    const float* W_pos       = (const float*)d_in[5];
    const float* b_pos       = (const float*)d_in[6];
    float* out = (float*)d_out;

    // zero accumulator + counts
    {
        size_t total = (size_t)N_NODES * D_PAD + N_NODES;
        int blocks = (int)((total + 255) / 256);
        zero_kernel<<<blocks, 256>>>();
    }
    // gating table
    gating_kernel<<<N_POS, 256>>>(W_pos, b_pos);
    // prop GEMM
    {
        dim3 grid((DE + BN - 1) / BN, (N_NODES + BM - 1) / BM);
        gemm_prop_kernel<<<grid, 256>>>(node_states, W_transform, b_transform);
    }
    // edge scatter (warp per edge, 8 warps/block)
    {
        int blocks = (N_EDGES_TOTAL + 7) / 8;
        scatter_kernel<<<blocks, 256>>>(edges, pos_lists);
    }
    // normalize into d_out
    {
        int blocks = (N_NODES * D + 255) / 256;
        divide_kernel<<<blocks, 256>>>(out);
    }
}

// round 5
// speedup vs baseline: 2.5684x; 2.5684x over previous
#include <cuda_runtime.h>
#include <math.h>
#include <stdint.h>

#define N_NODES 100000
#define D 202
#define D_PAD 204            // padded row for 16B-aligned v4 atomics
#define E_TYPES 6
#define M_EDGES 200000
#define N_POS 512
#define DE (D * E_TYPES)     // 1212
#define N_EDGES_TOTAL (E_TYPES * M_EDGES)  // 1,200,000

// ---------------- device scratch (no allocations allowed) ----------------
__device__ float g_prop[(size_t)N_NODES * DE];     // 485 MB: node_states @ W_transform + b
__device__ float g_gate[N_POS * D];                // 2*sigmoid(pos_emb @ W_pos + b_pos)
__device__ float g_acc[(size_t)N_NODES * D_PAD];   // padded accumulator (16B-aligned rows)
__device__ float g_cnt[N_NODES];                   // per-target edge count

// ---------------- zero accumulator + counts ----------------
__global__ void zero_kernel() {
    size_t i = (size_t)blockIdx.x * blockDim.x + threadIdx.x;
    size_t total_acc = (size_t)N_NODES * D_PAD;
    if (i < total_acc) g_acc[i] = 0.0f;
    else if (i < total_acc + N_NODES) g_cnt[i - total_acc] = 0.0f;
}

// ---------------- position gating table: 512 x 202 ----------------
__global__ void gating_kernel(const float* __restrict__ W_pos,
                              const float* __restrict__ b_pos) {
    __shared__ float emb[D];
    int p = blockIdx.x;
    int t = threadIdx.x;
    if (t < 100) {
        float inv = powf(10000.0f, -(float)t / 100.0f);
        float s = (float)p * inv;
        emb[t]       = sinf(s);
        emb[100 + t] = cosf(s);
    }
    if (t == 100) { emb[200] = 0.0f; emb[201] = 0.0f; }
    __syncthreads();
    for (int c = t; c < D; c += blockDim.x) {
        float acc = b_pos[c];
        #pragma unroll 4
        for (int k = 0; k < 200; k++)        // rows 200,201 of emb are zero
            acc += emb[k] * W_pos[k * D + c];
        g_gate[p * D + c] = 2.0f / (1.0f + expf(-acc));
    }
}

// ---------------- TF32 tensor-core GEMM ----------------
// C[100000,1212] = A[100000,202] @ W[202,1212] + b
// CTA tile 128x128, 8 warps (2 M x 4 N), warp tile 64x32,
// mma.sync m16n8k8 tf32, K padded to 208.
#define GBM 128
#define GBN 128
#define GBK 16
#define A_STRIDE (GBK + 4)     // 20: conflict-free fragment loads
#define B_STRIDE (GBN + 8)     // 136: conflict-free fragment loads

__device__ __forceinline__ uint32_t f2tf32(float x) {
    uint32_t r;
    asm("cvt.rna.tf32.f32 %0, %1;" : "=r"(r) : "f"(x));
    return r;
}

__global__ __launch_bounds__(256)
void gemm_tf32_kernel(const float* __restrict__ A,
                      const float* __restrict__ W,
                      const float* __restrict__ bias) {
    __shared__ uint32_t As[GBM * A_STRIDE];   // 128 x 20 -> 10.0 KB
    __shared__ uint32_t Bs[GBK * B_STRIDE];   // 16 x 136 ->  8.5 KB

    const int tid  = threadIdx.x;
    const int lane = tid & 31;
    const int warp = tid >> 5;
    const int gid  = lane >> 2;   // 0..7 (groupID)
    const int tig  = lane & 3;    // 0..3 (thread-in-group)
    const int wm   = (warp & 1) * 64;    // warp M offset in CTA tile
    const int wn   = (warp >> 1) * 32;   // warp N offset in CTA tile

    const int bm = blockIdx.y * GBM;
    const int bn = blockIdx.x * GBN;

    float c[4][4][4];
    #pragma unroll
    for (int mt = 0; mt < 4; mt++)
        #pragma unroll
        for (int nt = 0; nt < 4; nt++)
            #pragma unroll
            for (int r = 0; r < 4; r++) c[mt][nt][r] = 0.0f;

    for (int kk = 0; kk < 208; kk += GBK) {
        __syncthreads();
        // ---- load A tile: 128 rows x 16 cols as float2 (row base 8B-aligned) ----
        #pragma unroll
        for (int it = 0; it < 4; it++) {
            int f = tid + it * 256;          // float2 index, 0..1023
            int row = f >> 3;                // 0..127
            int col = (f & 7) * 2;           // 0,2,..,14
            int gm = bm + row, gk = kk + col;
            float2 v = make_float2(0.0f, 0.0f);
            if (gm < N_NODES && gk < D)      // D even: pair fully valid or fully out
                v = *(const float2*)(A + (size_t)gm * D + gk);
            As[row * A_STRIDE + col]     = f2tf32(v.x);
            As[row * A_STRIDE + col + 1] = f2tf32(v.y);
        }
        // ---- load W tile: 16 rows x 128 cols as float4 (row stride 4848B, 16B-aligned) ----
        #pragma unroll
        for (int it = 0; it < 2; it++) {
            int f = tid + it * 256;          // float4 index, 0..511
            int row = f >> 5;                // 0..15
            int col = (f & 31) * 4;          // 0,4,..,124
            int gk = kk + row, gn = bn + col;
            float4 v = make_float4(0.f, 0.f, 0.f, 0.f);
            if (gk < D && gn < DE)           // DE % 4 == 0: quad fully valid or out
                v = *(const float4*)(W + (size_t)gk * DE + gn);
            uint32_t* bp = Bs + row * B_STRIDE + col;
            bp[0] = f2tf32(v.x); bp[1] = f2tf32(v.y);
            bp[2] = f2tf32(v.z); bp[3] = f2tf32(v.w);
        }
        __syncthreads();

        // ---- compute: two k8 steps ----
        #pragma unroll
        for (int ks = 0; ks < 16; ks += 8) {
            uint32_t a[4][4];
            #pragma unroll
            for (int mt = 0; mt < 4; mt++) {
                int r0 = wm + mt * 16 + gid;
                a[mt][0] = As[r0 * A_STRIDE + ks + tig];
                a[mt][1] = As[(r0 + 8) * A_STRIDE + ks + tig];
                a[mt][2] = As[r0 * A_STRIDE + ks + tig + 4];
                a[mt][3] = As[(r0 + 8) * A_STRIDE + ks + tig + 4];
            }
            uint32_t b[4][2];
            #pragma unroll
            for (int nt = 0; nt < 4; nt++) {
                int cn = wn + nt * 8 + gid;
                b[nt][0] = Bs[(ks + tig) * B_STRIDE + cn];
                b[nt][1] = Bs[(ks + tig + 4) * B_STRIDE + cn];
            }
            #pragma unroll
            for (int mt = 0; mt < 4; mt++)
                #pragma unroll
                for (int nt = 0; nt < 4; nt++) {
                    asm volatile(
                        "mma.sync.aligned.m16n8k8.row.col.f32.tf32.tf32.f32 "
                        "{%0,%1,%2,%3}, {%4,%5,%6,%7}, {%8,%9}, {%0,%1,%2,%3};"
                        : "+f"(c[mt][nt][0]), "+f"(c[mt][nt][1]),
                          "+f"(c[mt][nt][2]), "+f"(c[mt][nt][3])
                        : "r"(a[mt][0]), "r"(a[mt][1]), "r"(a[mt][2]), "r"(a[mt][3]),
                          "r"(b[nt][0]), "r"(b[nt][1]));
                }
        }
    }

    // ---- epilogue: bias add + store (float2 pairs, col0 even) ----
    #pragma unroll
    for (int mt = 0; mt < 4; mt++) {
        int row0 = bm + wm + mt * 16 + gid;
        #pragma unroll
        for (int nt = 0; nt < 4; nt++) {
            int col0 = bn + wn + nt * 8 + tig * 2;
            if (col0 >= DE) continue;
            float b0 = bias[col0], b1 = bias[col0 + 1];
            if (row0 < N_NODES) {
                float2 v = make_float2(c[mt][nt][0] + b0, c[mt][nt][1] + b1);
                *(float2*)(g_prop + (size_t)row0 * DE + col0) = v;
            }
            if (row0 + 8 < N_NODES) {
                float2 v = make_float2(c[mt][nt][2] + b0, c[mt][nt][3] + b1);
                *(float2*)(g_prop + (size_t)(row0 + 8) * DE + col0) = v;
            }
        }
    }
}

// ---------------- edge scatter: warp per edge, vectorized red.global ----------------
__global__ __launch_bounds__(256)
void scatter_kernel(const int* __restrict__ edges,
                    const int* __restrict__ pos_lists) {
    int w = (int)((blockIdx.x * (size_t)blockDim.x + threadIdx.x) >> 5);
    int lane = threadIdx.x & 31;
    if (w >= N_EDGES_TOTAL) return;

    int e = w / M_EDGES;
    int m = w - e * M_EDGES;
    int eidx = e * M_EDGES + m;
    int src = edges[2 * eidx + 0];
    int tgt = edges[2 * eidx + 1];
    int p   = pos_lists[eidx];

    const float2* pr2 = (const float2*)(g_prop + (size_t)src * DE + (size_t)e * D);
    const float2* gt2 = (const float2*)(g_gate + (size_t)p * D);
    float* op = g_acc + (size_t)tgt * D_PAD;   // 16B-aligned rows

    for (int j4 = lane; j4 < 50; j4 += 32) {
        float2 a0 = pr2[2 * j4];
        float2 a1 = pr2[2 * j4 + 1];
        float2 g0 = gt2[2 * j4];
        float2 g1 = gt2[2 * j4 + 1];
        float v0 = a0.x * g0.x;
        float v1 = a0.y * g0.y;
        float v2 = a1.x * g1.x;
        float v3 = a1.y * g1.y;
        asm volatile("red.global.add.v4.f32 [%0], {%1, %2, %3, %4};"
                     :: "l"(op + 4 * j4), "f"(v0), "f"(v1), "f"(v2), "f"(v3)
                     : "memory");
    }
    if (lane == 31) {
        float2 a = pr2[100];
        float2 g = gt2[100];
        float v0 = a.x * g.x;
        float v1 = a.y * g.y;
        asm volatile("red.global.add.v2.f32 [%0], {%1, %2};"
                     :: "l"(op + 200), "f"(v0), "f"(v1)
                     : "memory");
    }
    if (lane == 0) {
        atomicAdd(&g_cnt[tgt], 1.0f);
    }
}

// ---------------- normalize + write output ----------------
__global__ void divide_kernel(float* __restrict__ out) {
    int i = blockIdx.x * blockDim.x + threadIdx.x;
    if (i >= N_NODES * D) return;
    int n = i / D;
    int c = i - n * D;
    float cnt = g_cnt[n];
    float div = (cnt == 0.0f ? 1.0f : cnt) + 1e-8f;
    out[i] = g_acc[(size_t)n * D_PAD + c] / div;
}

// ---------------- launch ----------------
extern "C" void kernel_launch(void* const* d_in, const int* in_sizes, int n_in,
                              void* d_out, int out_size) {
    const float* node_states = (const float*)d_in[0];
    const int*   edges       = (const int*)  d_in[1];
    const int*   pos_lists   = (const int*)  d_in[2];
    const float* W_transform = (const float*)d_in[3];
    const float* b_transform = (const float*)d_in[4];
    const float* W_pos       = (const float*)d_in[5];
    const float* b_pos       = (const float*)d_in[6];
    float* out = (float*)d_out;

    // zero accumulator + counts
    {
        size_t total = (size_t)N_NODES * D_PAD + N_NODES;
        int blocks = (int)((total + 255) / 256);
        zero_kernel<<<blocks, 256>>>();
    }
    // gating table
    gating_kernel<<<N_POS, 256>>>(W_pos, b_pos);
    // prop GEMM (tf32 tensor cores)
    {
        dim3 grid((DE + GBN - 1) / GBN, (N_NODES + GBM - 1) / GBM);
        gemm_tf32_kernel<<<grid, 256>>>(node_states, W_transform, b_transform);
    }
    // edge scatter (warp per edge, 8 warps/block)
    {
        int blocks = (N_EDGES_TOTAL + 7) / 8;
        scatter_kernel<<<blocks, 256>>>(edges, pos_lists);
    }
    // normalize into d_out
    {
        int blocks = (N_NODES * D + 255) / 256;
        divide_kernel<<<blocks, 256>>>(out);
    }
}

// round 7
// speedup vs baseline: 2.6107x; 1.0165x over previous
#include <cuda_runtime.h>
#include <math.h>
#include <stdint.h>

#define N_NODES 100000
#define D 202
#define D_PAD 204            // padded row for 16B-aligned v4 atomics
#define E_TYPES 6
#define M_EDGES 200000
#define N_POS 512
#define DE (D * E_TYPES)     // 1212
#define N_EDGES_TOTAL (E_TYPES * M_EDGES)  // 1,200,000

// ---------------- device scratch (no allocations allowed) ----------------
__device__ float g_prop[(size_t)N_NODES * DE];     // 485 MB
__device__ float g_gate[N_POS * D];
__device__ float g_acc[(size_t)N_NODES * D_PAD];
__device__ float g_cnt[N_NODES];

// ---------------- zero accumulator + counts ----------------
__global__ void zero_kernel() {
    size_t i = (size_t)blockIdx.x * blockDim.x + threadIdx.x;
    size_t total_acc = (size_t)N_NODES * D_PAD;
    if (i < total_acc) g_acc[i] = 0.0f;
    else if (i < total_acc + N_NODES) g_cnt[i - total_acc] = 0.0f;
}

// ---------------- position gating table: 512 x 202 ----------------
__global__ void gating_kernel(const float* __restrict__ W_pos,
                              const float* __restrict__ b_pos) {
    __shared__ float emb[D];
    int p = blockIdx.x;
    int t = threadIdx.x;
    if (t < 100) {
        float inv = powf(10000.0f, -(float)t / 100.0f);
        float s = (float)p * inv;
        emb[t]       = sinf(s);
        emb[100 + t] = cosf(s);
    }
    if (t == 100) { emb[200] = 0.0f; emb[201] = 0.0f; }
    __syncthreads();
    for (int c = t; c < D; c += blockDim.x) {
        float acc = b_pos[c];
        #pragma unroll 4
        for (int k = 0; k < 200; k++)
            acc += emb[k] * W_pos[k * D + c];
        g_gate[p * D + c] = 2.0f / (1.0f + expf(-acc));
    }
}

// ---------------- TF32 tensor-core GEMM (software-pipelined) ----------------
// C[100000,1212] = A[100000,202] @ W[202,1212] + b
// CTA tile 128x128, 8 warps (2M x 4N), warp tile 64x32, mma m16n8k8 tf32.
// K padded 202 -> 208 (13 tiles of 16).
#define GBM 128
#define GBN 128
#define GBK 16
#define NKT 13                 // 208/16
#define A_STRIDE (GBK + 4)     // 20
#define B_STRIDE (GBN + 8)     // 136

__device__ __forceinline__ uint32_t f2tf32(float x) {
    uint32_t r;
    asm("cvt.rna.tf32.f32 %0, %1;" : "=r"(r) : "f"(x));
    return r;
}

__global__ __launch_bounds__(256)
void gemm_tf32_kernel(const float* __restrict__ A,
                      const float* __restrict__ W,
                      const float* __restrict__ bias) {
    __shared__ uint32_t As[GBM * A_STRIDE];   // 10.0 KB
    __shared__ uint32_t Bs[GBK * B_STRIDE];   //  8.5 KB

    const int tid  = threadIdx.x;
    const int lane = tid & 31;
    const int warp = tid >> 5;
    const int gid  = lane >> 2;
    const int tig  = lane & 3;
    const int wm   = (warp & 1) * 64;
    const int wn   = (warp >> 1) * 32;

    const int bm = blockIdx.y * GBM;
    const int bn = blockIdx.x * GBN;

    // A-tile load mapping (4 float2 per thread)
    const int ar_row = tid >> 3;            // row for it=0 (rows advance by 32 per it)
    const int ar_col = (tid & 7) * 2;
    // B-tile load mapping (2 float4 per thread)
    const int br_row = tid >> 5;            // row for it=0 (rows advance by 8 per it)
    const int br_col = (tid & 31) * 4;

    float c[4][4][4];
    #pragma unroll
    for (int mt = 0; mt < 4; mt++)
        #pragma unroll
        for (int nt = 0; nt < 4; nt++)
            #pragma unroll
            for (int r = 0; r < 4; r++) c[mt][nt][r] = 0.0f;

    float2 pa[4];
    float4 pw[2];

    // ---- prefetch tile 0 into registers ----
    {
        const int kk = 0;
        #pragma unroll
        for (int it = 0; it < 4; it++) {
            int gm = bm + ar_row + it * 32, gk = kk + ar_col;
            pa[it] = make_float2(0.f, 0.f);
            if (gm < N_NODES && gk < D)
                pa[it] = *(const float2*)(A + (size_t)gm * D + gk);
        }
        #pragma unroll
        for (int it = 0; it < 2; it++) {
            int gk = kk + br_row + it * 8, gn = bn + br_col;
            pw[it] = make_float4(0.f, 0.f, 0.f, 0.f);
            if (gk < D && gn < DE)
                pw[it] = *(const float4*)(W + (size_t)gk * DE + gn);
        }
    }
    // ---- store tile 0 to smem (with cvt) ----
    #pragma unroll
    for (int it = 0; it < 4; it++) {
        uint32_t* ap = As + (ar_row + it * 32) * A_STRIDE + ar_col;
        ap[0] = f2tf32(pa[it].x); ap[1] = f2tf32(pa[it].y);
    }
    #pragma unroll
    for (int it = 0; it < 2; it++) {
        uint32_t* bp = Bs + (br_row + it * 8) * B_STRIDE + br_col;
        bp[0] = f2tf32(pw[it].x); bp[1] = f2tf32(pw[it].y);
        bp[2] = f2tf32(pw[it].z); bp[3] = f2tf32(pw[it].w);
    }

    for (int iter = 0; iter < NKT; iter++) {
        __syncthreads();

        // ---- prefetch next tile into registers (LDGs issue first, overlap compute) ----
        if (iter + 1 < NKT) {
            const int kk = (iter + 1) * GBK;
            #pragma unroll
            for (int it = 0; it < 4; it++) {
                int gm = bm + ar_row + it * 32, gk = kk + ar_col;
                pa[it] = make_float2(0.f, 0.f);
                if (gm < N_NODES && gk < D)
                    pa[it] = *(const float2*)(A + (size_t)gm * D + gk);
            }
            #pragma unroll
            for (int it = 0; it < 2; it++) {
                int gk = kk + br_row + it * 8, gn = bn + br_col;
                pw[it] = make_float4(0.f, 0.f, 0.f, 0.f);
                if (gk < D && gn < DE)
                    pw[it] = *(const float4*)(W + (size_t)gk * DE + gn);
            }
        }

        // ---- compute current tile from smem ----
        #pragma unroll
        for (int ks = 0; ks < 16; ks += 8) {
            uint32_t a[4][4];
            #pragma unroll
            for (int mt = 0; mt < 4; mt++) {
                int r0 = wm + mt * 16 + gid;
                a[mt][0] = As[r0 * A_STRIDE + ks + tig];
                a[mt][1] = As[(r0 + 8) * A_STRIDE + ks + tig];
                a[mt][2] = As[r0 * A_STRIDE + ks + tig + 4];
                a[mt][3] = As[(r0 + 8) * A_STRIDE + ks + tig + 4];
            }
            uint32_t b[4][2];
            #pragma unroll
            for (int nt = 0; nt < 4; nt++) {
                int cn = wn + nt * 8 + gid;
                b[nt][0] = Bs[(ks + tig) * B_STRIDE + cn];
                b[nt][1] = Bs[(ks + tig + 4) * B_STRIDE + cn];
            }
            #pragma unroll
            for (int mt = 0; mt < 4; mt++)
                #pragma unroll
                for (int nt = 0; nt < 4; nt++) {
                    asm volatile(
                        "mma.sync.aligned.m16n8k8.row.col.f32.tf32.tf32.f32 "
                        "{%0,%1,%2,%3}, {%4,%5,%6,%7}, {%8,%9}, {%0,%1,%2,%3};"
                        : "+f"(c[mt][nt][0]), "+f"(c[mt][nt][1]),
                          "+f"(c[mt][nt][2]), "+f"(c[mt][nt][3])
                        : "r"(a[mt][0]), "r"(a[mt][1]), "r"(a[mt][2]), "r"(a[mt][3]),
                          "r"(b[nt][0]), "r"(b[nt][1]));
                }
        }

        __syncthreads();

        // ---- store prefetched tile to smem (with cvt) ----
        if (iter + 1 < NKT) {
            #pragma unroll
            for (int it = 0; it < 4; it++) {
                uint32_t* ap = As + (ar_row + it * 32) * A_STRIDE + ar_col;
                ap[0] = f2tf32(pa[it].x); ap[1] = f2tf32(pa[it].y);
            }
            #pragma unroll
            for (int it = 0; it < 2; it++) {
                uint32_t* bp = Bs + (br_row + it * 8) * B_STRIDE + br_col;
                bp[0] = f2tf32(pw[it].x); bp[1] = f2tf32(pw[it].y);
                bp[2] = f2tf32(pw[it].z); bp[3] = f2tf32(pw[it].w);
            }
        }
    }

    // ---- epilogue: bias add + store ----
    #pragma unroll
    for (int mt = 0; mt < 4; mt++) {
        int row0 = bm + wm + mt * 16 + gid;
        #pragma unroll
        for (int nt = 0; nt < 4; nt++) {
            int col0 = bn + wn + nt * 8 + tig * 2;
            if (col0 >= DE) continue;
            float b0 = bias[col0], b1 = bias[col0 + 1];
            if (row0 < N_NODES) {
                float2 v = make_float2(c[mt][nt][0] + b0, c[mt][nt][1] + b1);
                *(float2*)(g_prop + (size_t)row0 * DE + col0) = v;
            }
            if (row0 + 8 < N_NODES) {
                float2 v = make_float2(c[mt][nt][2] + b0, c[mt][nt][3] + b1);
                *(float2*)(g_prop + (size_t)(row0 + 8) * DE + col0) = v;
            }
        }
    }
}

// ---------------- edge scatter: warp per edge, vectorized red.global ----------------
__global__ __launch_bounds__(256)
void scatter_kernel(const int* __restrict__ edges,
                    const int* __restrict__ pos_lists) {
    int w = (int)((blockIdx.x * (size_t)blockDim.x + threadIdx.x) >> 5);
    int lane = threadIdx.x & 31;
    if (w >= N_EDGES_TOTAL) return;

    int e = w / M_EDGES;
    int m = w - e * M_EDGES;
    int eidx = e * M_EDGES + m;
    int src = edges[2 * eidx + 0];
    int tgt = edges[2 * eidx + 1];
    int p   = pos_lists[eidx];

    const float2* pr2 = (const float2*)(g_prop + (size_t)src * DE + (size_t)e * D);
    const float2* gt2 = (const float2*)(g_gate + (size_t)p * D);
    float* op = g_acc + (size_t)tgt * D_PAD;

    for (int j4 = lane; j4 < 50; j4 += 32) {
        float2 a0 = pr2[2 * j4];
        float2 a1 = pr2[2 * j4 + 1];
        float2 g0 = gt2[2 * j4];
        float2 g1 = gt2[2 * j4 + 1];
        float v0 = a0.x * g0.x;
        float v1 = a0.y * g0.y;
        float v2 = a1.x * g1.x;
        float v3 = a1.y * g1.y;
        asm volatile("red.global.add.v4.f32 [%0], {%1, %2, %3, %4};"
                     :: "l"(op + 4 * j4), "f"(v0), "f"(v1), "f"(v2), "f"(v3)
                     : "memory");
    }
    if (lane == 31) {
        float2 a = pr2[100];
        float2 g = gt2[100];
        float v0 = a.x * g.x;
        float v1 = a.y * g.y;
        asm volatile("red.global.add.v2.f32 [%0], {%1, %2};"
                     :: "l"(op + 200), "f"(v0), "f"(v1)
                     : "memory");
    }
    if (lane == 0) {
        atomicAdd(&g_cnt[tgt], 1.0f);
    }
}

// ---------------- normalize + write output ----------------
__global__ void divide_kernel(float* __restrict__ out) {
    int i = blockIdx.x * blockDim.x + threadIdx.x;
    if (i >= N_NODES * D) return;
    int n = i / D;
    int c = i - n * D;
    float cnt = g_cnt[n];
    float div = (cnt == 0.0f ? 1.0f : cnt) + 1e-8f;
    out[i] = g_acc[(size_t)n * D_PAD + c] / div;
}

// ---------------- launch ----------------
extern "C" void kernel_launch(void* const* d_in, const int* in_sizes, int n_in,
                              void* d_out, int out_size) {
    const float* node_states = (const float*)d_in[0];
    const int*   edges       = (const int*)  d_in[1];
    const int*   pos_lists   = (const int*)  d_in[2];
    const float* W_transform = (const float*)d_in[3];
    const float* b_transform = (const float*)d_in[4];
    const float* W_pos       = (const float*)d_in[5];
    const float* b_pos       = (const float*)d_in[6];
    float* out = (float*)d_out;

    {
        size_t total = (size_t)N_NODES * D_PAD + N_NODES;
        int blocks = (int)((total + 255) / 256);
        zero_kernel<<<blocks, 256>>>();
    }
    gating_kernel<<<N_POS, 256>>>(W_pos, b_pos);
    {
        dim3 grid((DE + GBN - 1) / GBN, (N_NODES + GBM - 1) / GBM);
        gemm_tf32_kernel<<<grid, 256>>>(node_states, W_transform, b_transform);
    }
    {
        int blocks = (N_EDGES_TOTAL + 7) / 8;
        scatter_kernel<<<blocks, 256>>>(edges, pos_lists);
    }
    {
        int blocks = (N_NODES * D + 255) / 256;
        divide_kernel<<<blocks, 256>>>(out);
    }
}

// round 9
// speedup vs baseline: 2.8016x; 1.0731x over previous
#include <cuda_runtime.h>
#include <cuda_fp16.h>
#include <math.h>
#include <stdint.h>

#define N_NODES 100000
#define D 202
#define D_PAD 204
#define E_TYPES 6
#define M_EDGES 200000
#define N_POS 512
#define DE (D * E_TYPES)     // 1212
#define N_EDGES_TOTAL (E_TYPES * M_EDGES)
#define KP 208               // K padded to 13 tiles of 16

// ---------------- device scratch ----------------
__device__ float g_prop[(size_t)N_NODES * DE];     // 485 MB
__device__ float g_gate[N_POS * D];
__device__ float g_acc[(size_t)N_NODES * D_PAD];
__device__ float g_cnt[N_NODES];
__device__ __align__(16) __half g_Ah[(size_t)N_NODES * KP];  // 41.6 MB, K-major
__device__ __align__(16) __half g_Bt[(size_t)DE * KP];       // W^T, K-major

// ---------------- zero accumulator + counts ----------------
__global__ void zero_kernel() {
    size_t i = (size_t)blockIdx.x * blockDim.x + threadIdx.x;
    size_t total_acc = (size_t)N_NODES * D_PAD;
    if (i < total_acc) g_acc[i] = 0.0f;
    else if (i < total_acc + N_NODES) g_cnt[i - total_acc] = 0.0f;
}

// ---------------- position gating table ----------------
__global__ void gating_kernel(const float* __restrict__ W_pos,
                              const float* __restrict__ b_pos) {
    __shared__ float emb[D];
    int p = blockIdx.x;
    int t = threadIdx.x;
    if (t < 100) {
        float inv = powf(10000.0f, -(float)t / 100.0f);
        float s = (float)p * inv;
        emb[t]       = sinf(s);
        emb[100 + t] = cosf(s);
    }
    if (t == 100) { emb[200] = 0.0f; emb[201] = 0.0f; }
    __syncthreads();
    for (int c = t; c < D; c += blockDim.x) {
        float acc = b_pos[c];
        #pragma unroll 4
        for (int k = 0; k < 200; k++)
            acc += emb[k] * W_pos[k * D + c];
        g_gate[p * D + c] = 2.0f / (1.0f + expf(-acc));
    }
}

// ---------------- convert A -> fp16, K padded (row-major [N, KP]) ----------------
__global__ void convertA_kernel(const float* __restrict__ A) {
    int i = blockIdx.x * blockDim.x + threadIdx.x;   // over N_NODES * (KP/2) pairs
    if (i >= N_NODES * (KP / 2)) return;
    int n  = i / (KP / 2);
    int kp = (i - n * (KP / 2)) * 2;
    float v0 = (kp     < D) ? A[(size_t)n * D + kp]     : 0.0f;
    float v1 = (kp + 1 < D) ? A[(size_t)n * D + kp + 1] : 0.0f;
    ((__half2*)g_Ah)[i] = __floats2half2_rn(v0, v1);
}

// ---------------- transpose + convert W -> fp16 [DE, KP] K-major ----------------
__global__ void convertW_kernel(const float* __restrict__ W) {
    int i = blockIdx.x * blockDim.x + threadIdx.x;   // over DE * (KP/2) pairs
    if (i >= DE * (KP / 2)) return;
    int n  = i / (KP / 2);
    int kp = (i - n * (KP / 2)) * 2;
    float v0 = (kp     < D) ? W[(size_t)kp * DE + n]       : 0.0f;
    float v1 = (kp + 1 < D) ? W[(size_t)(kp + 1) * DE + n] : 0.0f;
    ((__half2*)g_Bt)[i] = __floats2half2_rn(v0, v1);
}

// ---------------- FP16 tensor-core GEMM (m16n8k16, software-pipelined) ----------------
// C[100000,1212] = A[100000,KP] @ Bt[1212,KP]^T + bias
// CTA tile 128x128, 8 warps (2M x 4N), warp tile 64x32. 13 K-tiles of 16.
#define NKT 13
#define A_ST 9       // A2s row stride in uint32 (8 half2 + 1 pad)
#define B_ST 136     // B2s k2-row stride in uint32 (conflict-free: 136%32=8)

__global__ __launch_bounds__(256)
void gemm_fp16_kernel(const float* __restrict__ bias) {
    __shared__ uint32_t A2s[128 * A_ST];   // 4.6 KB: half2-packed A tile [row][k2]
    __shared__ uint32_t B2s[8 * B_ST];     // 4.3 KB: half2-packed B tile [k2][n]

    const int tid  = threadIdx.x;
    const int lane = tid & 31;
    const int warp = tid >> 5;
    const int gid  = lane >> 2;    // 0..7
    const int tig  = lane & 3;     // 0..3
    const int wm   = (warp & 1) * 64;
    const int wn   = (warp >> 1) * 32;

    const int bm = blockIdx.y * 128;
    const int bn = blockIdx.x * 128;

    // load mappings: thread t -> (row/col = t>>1, halfchunk = t&1)
    const int l_row  = tid >> 1;    // 0..127
    const int l_half = tid & 1;     // 0 or 1 (k offset 0 or 8 halves)

    float c[4][4][4];
    #pragma unroll
    for (int mt = 0; mt < 4; mt++)
        #pragma unroll
        for (int nt = 0; nt < 4; nt++)
            #pragma unroll
            for (int r = 0; r < 4; r++) c[mt][nt][r] = 0.0f;

    uint4 pa, pb;

    // ---- prefetch tile 0 ----
    {
        int gm = bm + l_row;
        pa = make_uint4(0u, 0u, 0u, 0u);
        if (gm < N_NODES)
            pa = *(const uint4*)(g_Ah + (size_t)gm * KP + l_half * 8);
        int gn = bn + l_row;
        pb = make_uint4(0u, 0u, 0u, 0u);
        if (gn < DE)
            pb = *(const uint4*)(g_Bt + (size_t)gn * KP + l_half * 8);
    }
    // ---- store tile 0 ----
    {
        uint32_t* ap = A2s + l_row * A_ST + l_half * 4;
        ap[0] = pa.x; ap[1] = pa.y; ap[2] = pa.z; ap[3] = pa.w;
        uint32_t* bp = B2s + l_half * 4 * B_ST + l_row;
        bp[0] = pb.x; bp[B_ST] = pb.y; bp[2 * B_ST] = pb.z; bp[3 * B_ST] = pb.w;
    }

    for (int iter = 0; iter < NKT; iter++) {
        __syncthreads();

        // ---- prefetch next tile (LDGs first, overlap with MMA phase) ----
        if (iter + 1 < NKT) {
            const int kk = (iter + 1) * 16;
            int gm = bm + l_row;
            pa = make_uint4(0u, 0u, 0u, 0u);
            if (gm < N_NODES)
                pa = *(const uint4*)(g_Ah + (size_t)gm * KP + kk + l_half * 8);
            int gn = bn + l_row;
            pb = make_uint4(0u, 0u, 0u, 0u);
            if (gn < DE)
                pb = *(const uint4*)(g_Bt + (size_t)gn * KP + kk + l_half * 8);
        }

        // ---- compute current tile: one k16 step, 16 MMAs ----
        {
            uint32_t a[4][4];
            #pragma unroll
            for (int mt = 0; mt < 4; mt++) {
                int r0 = wm + mt * 16 + gid;
                a[mt][0] = A2s[r0 * A_ST + tig];
                a[mt][1] = A2s[(r0 + 8) * A_ST + tig];
                a[mt][2] = A2s[r0 * A_ST + tig + 4];
                a[mt][3] = A2s[(r0 + 8) * A_ST + tig + 4];
            }
            uint32_t b[4][2];
            #pragma unroll
            for (int nt = 0; nt < 4; nt++) {
                int cn = wn + nt * 8 + gid;
                b[nt][0] = B2s[tig * B_ST + cn];
                b[nt][1] = B2s[(tig + 4) * B_ST + cn];
            }
            #pragma unroll
            for (int mt = 0; mt < 4; mt++)
                #pragma unroll
                for (int nt = 0; nt < 4; nt++) {
                    asm volatile(
                        "mma.sync.aligned.m16n8k16.row.col.f32.f16.f16.f32 "
                        "{%0,%1,%2,%3}, {%4,%5,%6,%7}, {%8,%9}, {%0,%1,%2,%3};"
                        : "+f"(c[mt][nt][0]), "+f"(c[mt][nt][1]),
                          "+f"(c[mt][nt][2]), "+f"(c[mt][nt][3])
                        : "r"(a[mt][0]), "r"(a[mt][1]), "r"(a[mt][2]), "r"(a[mt][3]),
                          "r"(b[nt][0]), "r"(b[nt][1]));
                }
        }

        __syncthreads();

        // ---- store prefetched tile to smem ----
        if (iter + 1 < NKT) {
            uint32_t* ap = A2s + l_row * A_ST + l_half * 4;
            ap[0] = pa.x; ap[1] = pa.y; ap[2] = pa.z; ap[3] = pa.w;
            uint32_t* bp = B2s + l_half * 4 * B_ST + l_row;
            bp[0] = pb.x; bp[B_ST] = pb.y; bp[2 * B_ST] = pb.z; bp[3 * B_ST] = pb.w;
        }
    }

    // ---- epilogue: bias add + store ----
    #pragma unroll
    for (int mt = 0; mt < 4; mt++) {
        int row0 = bm + wm + mt * 16 + gid;
        #pragma unroll
        for (int nt = 0; nt < 4; nt++) {
            int col0 = bn + wn + nt * 8 + tig * 2;
            if (col0 >= DE) continue;
            float b0 = bias[col0], b1 = bias[col0 + 1];
            if (row0 < N_NODES) {
                float2 v = make_float2(c[mt][nt][0] + b0, c[mt][nt][1] + b1);
                *(float2*)(g_prop + (size_t)row0 * DE + col0) = v;
            }
            if (row0 + 8 < N_NODES) {
                float2 v = make_float2(c[mt][nt][2] + b0, c[mt][nt][3] + b1);
                *(float2*)(g_prop + (size_t)(row0 + 8) * DE + col0) = v;
            }
        }
    }
}

// ---------------- edge scatter (unchanged) ----------------
__global__ __launch_bounds__(256)
void scatter_kernel(const int* __restrict__ edges,
                    const int* __restrict__ pos_lists) {
    int w = (int)((blockIdx.x * (size_t)blockDim.x + threadIdx.x) >> 5);
    int lane = threadIdx.x & 31;
    if (w >= N_EDGES_TOTAL) return;

    int e = w / M_EDGES;
    int m = w - e * M_EDGES;
    int eidx = e * M_EDGES + m;
    int src = edges[2 * eidx + 0];
    int tgt = edges[2 * eidx + 1];
    int p   = pos_lists[eidx];

    const float2* pr2 = (const float2*)(g_prop + (size_t)src * DE + (size_t)e * D);
    const float2* gt2 = (const float2*)(g_gate + (size_t)p * D);
    float* op = g_acc + (size_t)tgt * D_PAD;

    for (int j4 = lane; j4 < 50; j4 += 32) {
        float2 a0 = pr2[2 * j4];
        float2 a1 = pr2[2 * j4 + 1];
        float2 g0 = gt2[2 * j4];
        float2 g1 = gt2[2 * j4 + 1];
        float v0 = a0.x * g0.x;
        float v1 = a0.y * g0.y;
        float v2 = a1.x * g1.x;
        float v3 = a1.y * g1.y;
        asm volatile("red.global.add.v4.f32 [%0], {%1, %2, %3, %4};"
                     :: "l"(op + 4 * j4), "f"(v0), "f"(v1), "f"(v2), "f"(v3)
                     : "memory");
    }
    if (lane == 31) {
        float2 a = pr2[100];
        float2 g = gt2[100];
        float v0 = a.x * g.x;
        float v1 = a.y * g.y;
        asm volatile("red.global.add.v2.f32 [%0], {%1, %2};"
                     :: "l"(op + 200), "f"(v0), "f"(v1)
                     : "memory");
    }
    if (lane == 0) {
        atomicAdd(&g_cnt[tgt], 1.0f);
    }
}

// ---------------- normalize + write output ----------------
__global__ void divide_kernel(float* __restrict__ out) {
    int i = blockIdx.x * blockDim.x + threadIdx.x;
    if (i >= N_NODES * D) return;
    int n = i / D;
    int c = i - n * D;
    float cnt = g_cnt[n];
    float div = (cnt == 0.0f ? 1.0f : cnt) + 1e-8f;
    out[i] = g_acc[(size_t)n * D_PAD + c] / div;
}

// ---------------- launch ----------------
extern "C" void kernel_launch(void* const* d_in, const int* in_sizes, int n_in,
                              void* d_out, int out_size) {
    const float* node_states = (const float*)d_in[0];
    const int*   edges       = (const int*)  d_in[1];
    const int*   pos_lists   = (const int*)  d_in[2];
    const float* W_transform = (const float*)d_in[3];
    const float* b_transform = (const float*)d_in[4];
    const float* W_pos       = (const float*)d_in[5];
    const float* b_pos       = (const float*)d_in[6];
    float* out = (float*)d_out;

    {
        size_t total = (size_t)N_NODES * D_PAD + N_NODES;
        int blocks = (int)((total + 255) / 256);
        zero_kernel<<<blocks, 256>>>();
    }
    gating_kernel<<<N_POS, 256>>>(W_pos, b_pos);
    {
        int n = N_NODES * (KP / 2);
        convertA_kernel<<<(n + 255) / 256, 256>>>(node_states);
    }
    {
        int n = DE * (KP / 2);
        convertW_kernel<<<(n + 255) / 256, 256>>>(W_transform);
    }
    {
        dim3 grid((DE + 127) / 128, (N_NODES + 127) / 128);
        gemm_fp16_kernel<<<grid, 256>>>(b_transform);
    }
    {
        int blocks = (N_EDGES_TOTAL + 7) / 8;
        scatter_kernel<<<blocks, 256>>>(edges, pos_lists);
    }
    {
        int blocks = (N_NODES * D + 255) / 256;
        divide_kernel<<<blocks, 256>>>(out);
    }
}

// round 10
// speedup vs baseline: 2.9624x; 1.0574x over previous
#include <cuda_runtime.h>
#include <cuda_fp16.h>
#include <math.h>
#include <stdint.h>

#define N_NODES 100000
#define D 202
#define D_PAD 204
#define E_TYPES 6
#define M_EDGES 200000
#define N_POS 512
#define DE (D * E_TYPES)     // 1212
#define N_EDGES_TOTAL (E_TYPES * M_EDGES)
#define KP 208               // K padded to 13 tiles of 16

// ---------------- device scratch ----------------
__device__ __align__(16) __half g_proph[(size_t)N_NODES * DE];  // 242 MB fp16 prop
__device__ float g_gate[N_POS * D];
__device__ float g_acc[(size_t)N_NODES * D_PAD];
__device__ float g_cnt[N_NODES];
__device__ __align__(16) __half g_Ah[(size_t)N_NODES * KP];  // 41.6 MB, K-major
__device__ __align__(16) __half g_Bt[(size_t)DE * KP];       // W^T, K-major

// ---------------- zero accumulator + counts ----------------
__global__ void zero_kernel() {
    size_t i = (size_t)blockIdx.x * blockDim.x + threadIdx.x;
    size_t total_acc = (size_t)N_NODES * D_PAD;
    if (i < total_acc) g_acc[i] = 0.0f;
    else if (i < total_acc + N_NODES) g_cnt[i - total_acc] = 0.0f;
}

// ---------------- position gating table ----------------
__global__ void gating_kernel(const float* __restrict__ W_pos,
                              const float* __restrict__ b_pos) {
    __shared__ float emb[D];
    int p = blockIdx.x;
    int t = threadIdx.x;
    if (t < 100) {
        float inv = powf(10000.0f, -(float)t / 100.0f);
        float s = (float)p * inv;
        emb[t]       = sinf(s);
        emb[100 + t] = cosf(s);
    }
    if (t == 100) { emb[200] = 0.0f; emb[201] = 0.0f; }
    __syncthreads();
    for (int c = t; c < D; c += blockDim.x) {
        float acc = b_pos[c];
        #pragma unroll 4
        for (int k = 0; k < 200; k++)
            acc += emb[k] * W_pos[k * D + c];
        g_gate[p * D + c] = 2.0f / (1.0f + expf(-acc));
    }
}

// ---------------- convert A -> fp16, K padded (row-major [N, KP]) ----------------
__global__ void convertA_kernel(const float* __restrict__ A) {
    int i = blockIdx.x * blockDim.x + threadIdx.x;
    if (i >= N_NODES * (KP / 2)) return;
    int n  = i / (KP / 2);
    int kp = (i - n * (KP / 2)) * 2;
    float v0 = (kp     < D) ? A[(size_t)n * D + kp]     : 0.0f;
    float v1 = (kp + 1 < D) ? A[(size_t)n * D + kp + 1] : 0.0f;
    ((__half2*)g_Ah)[i] = __floats2half2_rn(v0, v1);
}

// ---------------- transpose + convert W -> fp16 [DE, KP] K-major ----------------
__global__ void convertW_kernel(const float* __restrict__ W) {
    int i = blockIdx.x * blockDim.x + threadIdx.x;
    if (i >= DE * (KP / 2)) return;
    int n  = i / (KP / 2);
    int kp = (i - n * (KP / 2)) * 2;
    float v0 = (kp     < D) ? W[(size_t)kp * DE + n]       : 0.0f;
    float v1 = (kp + 1 < D) ? W[(size_t)(kp + 1) * DE + n] : 0.0f;
    ((__half2*)g_Bt)[i] = __floats2half2_rn(v0, v1);
}

// ---------------- FP16 tensor-core GEMM (m16n8k16, software-pipelined) ----------------
#define NKT 13
#define A_ST 9       // A2s row stride in uint32 (8 half2 + 1 pad)
#define B_ST 136     // B2s k2-row stride in uint32

__global__ __launch_bounds__(256)
void gemm_fp16_kernel(const float* __restrict__ bias) {
    __shared__ uint32_t A2s[128 * A_ST];
    __shared__ uint32_t B2s[8 * B_ST];

    const int tid  = threadIdx.x;
    const int lane = tid & 31;
    const int warp = tid >> 5;
    const int gid  = lane >> 2;
    const int tig  = lane & 3;
    const int wm   = (warp & 1) * 64;
    const int wn   = (warp >> 1) * 32;

    const int bm = blockIdx.y * 128;
    const int bn = blockIdx.x * 128;

    const int l_row  = tid >> 1;
    const int l_half = tid & 1;

    float c[4][4][4];
    #pragma unroll
    for (int mt = 0; mt < 4; mt++)
        #pragma unroll
        for (int nt = 0; nt < 4; nt++)
            #pragma unroll
            for (int r = 0; r < 4; r++) c[mt][nt][r] = 0.0f;

    uint4 pa, pb;

    // ---- prefetch tile 0 ----
    {
        int gm = bm + l_row;
        pa = make_uint4(0u, 0u, 0u, 0u);
        if (gm < N_NODES)
            pa = *(const uint4*)(g_Ah + (size_t)gm * KP + l_half * 8);
        int gn = bn + l_row;
        pb = make_uint4(0u, 0u, 0u, 0u);
        if (gn < DE)
            pb = *(const uint4*)(g_Bt + (size_t)gn * KP + l_half * 8);
    }
    {
        uint32_t* ap = A2s + l_row * A_ST + l_half * 4;
        ap[0] = pa.x; ap[1] = pa.y; ap[2] = pa.z; ap[3] = pa.w;
        uint32_t* bp = B2s + l_half * 4 * B_ST + l_row;
        bp[0] = pb.x; bp[B_ST] = pb.y; bp[2 * B_ST] = pb.z; bp[3 * B_ST] = pb.w;
    }

    for (int iter = 0; iter < NKT; iter++) {
        __syncthreads();

        if (iter + 1 < NKT) {
            const int kk = (iter + 1) * 16;
            int gm = bm + l_row;
            pa = make_uint4(0u, 0u, 0u, 0u);
            if (gm < N_NODES)
                pa = *(const uint4*)(g_Ah + (size_t)gm * KP + kk + l_half * 8);
            int gn = bn + l_row;
            pb = make_uint4(0u, 0u, 0u, 0u);
            if (gn < DE)
                pb = *(const uint4*)(g_Bt + (size_t)gn * KP + kk + l_half * 8);
        }

        {
            uint32_t a[4][4];
            #pragma unroll
            for (int mt = 0; mt < 4; mt++) {
                int r0 = wm + mt * 16 + gid;
                a[mt][0] = A2s[r0 * A_ST + tig];
                a[mt][1] = A2s[(r0 + 8) * A_ST + tig];
                a[mt][2] = A2s[r0 * A_ST + tig + 4];
                a[mt][3] = A2s[(r0 + 8) * A_ST + tig + 4];
            }
            uint32_t b[4][2];
            #pragma unroll
            for (int nt = 0; nt < 4; nt++) {
                int cn = wn + nt * 8 + gid;
                b[nt][0] = B2s[tig * B_ST + cn];
                b[nt][1] = B2s[(tig + 4) * B_ST + cn];
            }
            #pragma unroll
            for (int mt = 0; mt < 4; mt++)
                #pragma unroll
                for (int nt = 0; nt < 4; nt++) {
                    asm volatile(
                        "mma.sync.aligned.m16n8k16.row.col.f32.f16.f16.f32 "
                        "{%0,%1,%2,%3}, {%4,%5,%6,%7}, {%8,%9}, {%0,%1,%2,%3};"
                        : "+f"(c[mt][nt][0]), "+f"(c[mt][nt][1]),
                          "+f"(c[mt][nt][2]), "+f"(c[mt][nt][3])
                        : "r"(a[mt][0]), "r"(a[mt][1]), "r"(a[mt][2]), "r"(a[mt][3]),
                          "r"(b[nt][0]), "r"(b[nt][1]));
                }
        }

        __syncthreads();

        if (iter + 1 < NKT) {
            uint32_t* ap = A2s + l_row * A_ST + l_half * 4;
            ap[0] = pa.x; ap[1] = pa.y; ap[2] = pa.z; ap[3] = pa.w;
            uint32_t* bp = B2s + l_half * 4 * B_ST + l_row;
            bp[0] = pb.x; bp[B_ST] = pb.y; bp[2 * B_ST] = pb.z; bp[3 * B_ST] = pb.w;
        }
    }

    // ---- epilogue: bias add + fp16 store (half2 per row fragment) ----
    #pragma unroll
    for (int mt = 0; mt < 4; mt++) {
        int row0 = bm + wm + mt * 16 + gid;
        #pragma unroll
        for (int nt = 0; nt < 4; nt++) {
            int col0 = bn + wn + nt * 8 + tig * 2;
            if (col0 >= DE) continue;
            float b0 = bias[col0], b1 = bias[col0 + 1];
            if (row0 < N_NODES) {
                *(__half2*)(g_proph + (size_t)row0 * DE + col0) =
                    __floats2half2_rn(c[mt][nt][0] + b0, c[mt][nt][1] + b1);
            }
            if (row0 + 8 < N_NODES) {
                *(__half2*)(g_proph + (size_t)(row0 + 8) * DE + col0) =
                    __floats2half2_rn(c[mt][nt][2] + b0, c[mt][nt][3] + b1);
            }
        }
    }
}

// ---------------- edge scatter: fp16 gather, fp32 atomics ----------------
__global__ __launch_bounds__(256)
void scatter_kernel(const int* __restrict__ edges,
                    const int* __restrict__ pos_lists) {
    int w = (int)((blockIdx.x * (size_t)blockDim.x + threadIdx.x) >> 5);
    int lane = threadIdx.x & 31;
    if (w >= N_EDGES_TOTAL) return;

    int e = w / M_EDGES;
    int m = w - e * M_EDGES;
    int eidx = e * M_EDGES + m;
    int src = edges[2 * eidx + 0];
    int tgt = edges[2 * eidx + 1];
    int p   = pos_lists[eidx];

    // prop row base (halves): src*1212 + e*202 -> always even -> half2-aligned
    const __half2* pr2 = (const __half2*)(g_proph + (size_t)src * DE + (size_t)e * D);
    const float2*  gt2 = (const float2*)(g_gate + (size_t)p * D);
    float* op = g_acc + (size_t)tgt * D_PAD;

    // 50 groups of 4 elements: two half2 loads + one red.v4 (16B-aligned dest)
    for (int j4 = lane; j4 < 50; j4 += 32) {
        float2 a0 = __half22float2(pr2[2 * j4]);
        float2 a1 = __half22float2(pr2[2 * j4 + 1]);
        float2 g0 = gt2[2 * j4];
        float2 g1 = gt2[2 * j4 + 1];
        float v0 = a0.x * g0.x;
        float v1 = a0.y * g0.y;
        float v2 = a1.x * g1.x;
        float v3 = a1.y * g1.y;
        asm volatile("red.global.add.v4.f32 [%0], {%1, %2, %3, %4};"
                     :: "l"(op + 4 * j4), "f"(v0), "f"(v1), "f"(v2), "f"(v3)
                     : "memory");
    }
    if (lane == 31) {
        float2 a = __half22float2(pr2[100]);
        float2 g = gt2[100];
        float v0 = a.x * g.x;
        float v1 = a.y * g.y;
        asm volatile("red.global.add.v2.f32 [%0], {%1, %2};"
                     :: "l"(op + 200), "f"(v0), "f"(v1)
                     : "memory");
    }
    if (lane == 0) {
        atomicAdd(&g_cnt[tgt], 1.0f);
    }
}

// ---------------- normalize + write output ----------------
__global__ void divide_kernel(float* __restrict__ out) {
    int i = blockIdx.x * blockDim.x + threadIdx.x;
    if (i >= N_NODES * D) return;
    int n = i / D;
    int c = i - n * D;
    float cnt = g_cnt[n];
    float div = (cnt == 0.0f ? 1.0f : cnt) + 1e-8f;
    out[i] = g_acc[(size_t)n * D_PAD + c] / div;
}

// ---------------- launch ----------------
extern "C" void kernel_launch(void* const* d_in, const int* in_sizes, int n_in,
                              void* d_out, int out_size) {
    const float* node_states = (const float*)d_in[0];
    const int*   edges       = (const int*)  d_in[1];
    const int*   pos_lists   = (const int*)  d_in[2];
    const float* W_transform = (const float*)d_in[3];
    const float* b_transform = (const float*)d_in[4];
    const float* W_pos       = (const float*)d_in[5];
    const float* b_pos       = (const float*)d_in[6];
    float* out = (float*)d_out;

    {
        size_t total = (size_t)N_NODES * D_PAD + N_NODES;
        int blocks = (int)((total + 255) / 256);
        zero_kernel<<<blocks, 256>>>();
    }
    gating_kernel<<<N_POS, 256>>>(W_pos, b_pos);
    {
        int n = N_NODES * (KP / 2);
        convertA_kernel<<<(n + 255) / 256, 256>>>(node_states);
    }
    {
        int n = DE * (KP / 2);
        convertW_kernel<<<(n + 255) / 256, 256>>>(W_transform);
    }
    {
        dim3 grid((DE + 127) / 128, (N_NODES + 127) / 128);
        gemm_fp16_kernel<<<grid, 256>>>(b_transform);
    }
    {
        int blocks = (N_EDGES_TOTAL + 7) / 8;
        scatter_kernel<<<blocks, 256>>>(edges, pos_lists);
    }
    {
        int blocks = (N_NODES * D + 255) / 256;
        divide_kernel<<<blocks, 256>>>(out);
    }
}

// round 11
// speedup vs baseline: 3.7329x; 1.2601x over previous
#include <cuda_runtime.h>
#include <cuda_fp16.h>
#include <math.h>
#include <stdint.h>

#define N_NODES 100000
#define D 202
#define E_TYPES 6
#define M_EDGES 200000
#define N_POS 512
#define DE (D * E_TYPES)     // 1212
#define N_EDGES_TOTAL (E_TYPES * M_EDGES)
#define KP 208               // K padded to 13 tiles of 16
#define NBLK_SCAN 98         // ceil(100000/1024)

// ---------------- device scratch ----------------
__device__ __align__(16) __half g_proph[(size_t)N_NODES * DE];  // 242 MB fp16 prop
__device__ float g_gate[N_POS * D];
__device__ __align__(16) __half g_Ah[(size_t)N_NODES * KP];
__device__ __align__(16) __half g_Bt[(size_t)DE * KP];
__device__ int g_cnt_i[N_NODES];          // per-target degree (histogram)
__device__ int g_off[N_NODES];            // CSR offsets
__device__ int g_cur[N_NODES];            // running cursor for reorder
__device__ int g_sorted[N_EDGES_TOTAL];   // edge indices grouped by target
__device__ int g_bsum[NBLK_SCAN];         // per-block sums for scan

// ---------------- zero histogram ----------------
__global__ void zero_cnt_kernel() {
    int i = blockIdx.x * blockDim.x + threadIdx.x;
    if (i < N_NODES) g_cnt_i[i] = 0;
}

// ---------------- position gating table ----------------
__global__ void gating_kernel(const float* __restrict__ W_pos,
                              const float* __restrict__ b_pos) {
    __shared__ float emb[D];
    int p = blockIdx.x;
    int t = threadIdx.x;
    if (t < 100) {
        float inv = powf(10000.0f, -(float)t / 100.0f);
        float s = (float)p * inv;
        emb[t]       = sinf(s);
        emb[100 + t] = cosf(s);
    }
    if (t == 100) { emb[200] = 0.0f; emb[201] = 0.0f; }
    __syncthreads();
    for (int c = t; c < D; c += blockDim.x) {
        float acc = b_pos[c];
        #pragma unroll 4
        for (int k = 0; k < 200; k++)
            acc += emb[k] * W_pos[k * D + c];
        g_gate[p * D + c] = 2.0f / (1.0f + expf(-acc));
    }
}

// ---------------- convert A -> fp16, K padded ----------------
__global__ void convertA_kernel(const float* __restrict__ A) {
    int i = blockIdx.x * blockDim.x + threadIdx.x;
    if (i >= N_NODES * (KP / 2)) return;
    int n  = i / (KP / 2);
    int kp = (i - n * (KP / 2)) * 2;
    float v0 = (kp     < D) ? A[(size_t)n * D + kp]     : 0.0f;
    float v1 = (kp + 1 < D) ? A[(size_t)n * D + kp + 1] : 0.0f;
    ((__half2*)g_Ah)[i] = __floats2half2_rn(v0, v1);
}

// ---------------- transpose + convert W -> fp16 [DE, KP] K-major ----------------
__global__ void convertW_kernel(const float* __restrict__ W) {
    int i = blockIdx.x * blockDim.x + threadIdx.x;
    if (i >= DE * (KP / 2)) return;
    int n  = i / (KP / 2);
    int kp = (i - n * (KP / 2)) * 2;
    float v0 = (kp     < D) ? W[(size_t)kp * DE + n]       : 0.0f;
    float v1 = (kp + 1 < D) ? W[(size_t)(kp + 1) * DE + n] : 0.0f;
    ((__half2*)g_Bt)[i] = __floats2half2_rn(v0, v1);
}

// ---------------- FP16 tensor-core GEMM (m16n8k16, pipelined) ----------------
#define NKT 13
#define A_ST 9
#define B_ST 136

__global__ __launch_bounds__(256)
void gemm_fp16_kernel(const float* __restrict__ bias) {
    __shared__ uint32_t A2s[128 * A_ST];
    __shared__ uint32_t B2s[8 * B_ST];

    const int tid  = threadIdx.x;
    const int lane = tid & 31;
    const int warp = tid >> 5;
    const int gid  = lane >> 2;
    const int tig  = lane & 3;
    const int wm   = (warp & 1) * 64;
    const int wn   = (warp >> 1) * 32;

    const int bm = blockIdx.y * 128;
    const int bn = blockIdx.x * 128;

    const int l_row  = tid >> 1;
    const int l_half = tid & 1;

    float c[4][4][4];
    #pragma unroll
    for (int mt = 0; mt < 4; mt++)
        #pragma unroll
        for (int nt = 0; nt < 4; nt++)
            #pragma unroll
            for (int r = 0; r < 4; r++) c[mt][nt][r] = 0.0f;

    uint4 pa, pb;

    {
        int gm = bm + l_row;
        pa = make_uint4(0u, 0u, 0u, 0u);
        if (gm < N_NODES)
            pa = *(const uint4*)(g_Ah + (size_t)gm * KP + l_half * 8);
        int gn = bn + l_row;
        pb = make_uint4(0u, 0u, 0u, 0u);
        if (gn < DE)
            pb = *(const uint4*)(g_Bt + (size_t)gn * KP + l_half * 8);
    }
    {
        uint32_t* ap = A2s + l_row * A_ST + l_half * 4;
        ap[0] = pa.x; ap[1] = pa.y; ap[2] = pa.z; ap[3] = pa.w;
        uint32_t* bp = B2s + l_half * 4 * B_ST + l_row;
        bp[0] = pb.x; bp[B_ST] = pb.y; bp[2 * B_ST] = pb.z; bp[3 * B_ST] = pb.w;
    }

    for (int iter = 0; iter < NKT; iter++) {
        __syncthreads();

        if (iter + 1 < NKT) {
            const int kk = (iter + 1) * 16;
            int gm = bm + l_row;
            pa = make_uint4(0u, 0u, 0u, 0u);
            if (gm < N_NODES)
                pa = *(const uint4*)(g_Ah + (size_t)gm * KP + kk + l_half * 8);
            int gn = bn + l_row;
            pb = make_uint4(0u, 0u, 0u, 0u);
            if (gn < DE)
                pb = *(const uint4*)(g_Bt + (size_t)gn * KP + kk + l_half * 8);
        }

        {
            uint32_t a[4][4];
            #pragma unroll
            for (int mt = 0; mt < 4; mt++) {
                int r0 = wm + mt * 16 + gid;
                a[mt][0] = A2s[r0 * A_ST + tig];
                a[mt][1] = A2s[(r0 + 8) * A_ST + tig];
                a[mt][2] = A2s[r0 * A_ST + tig + 4];
                a[mt][3] = A2s[(r0 + 8) * A_ST + tig + 4];
            }
            uint32_t b[4][2];
            #pragma unroll
            for (int nt = 0; nt < 4; nt++) {
                int cn = wn + nt * 8 + gid;
                b[nt][0] = B2s[tig * B_ST + cn];
                b[nt][1] = B2s[(tig + 4) * B_ST + cn];
            }
            #pragma unroll
            for (int mt = 0; mt < 4; mt++)
                #pragma unroll
                for (int nt = 0; nt < 4; nt++) {
                    asm volatile(
                        "mma.sync.aligned.m16n8k16.row.col.f32.f16.f16.f32 "
                        "{%0,%1,%2,%3}, {%4,%5,%6,%7}, {%8,%9}, {%0,%1,%2,%3};"
                        : "+f"(c[mt][nt][0]), "+f"(c[mt][nt][1]),
                          "+f"(c[mt][nt][2]), "+f"(c[mt][nt][3])
                        : "r"(a[mt][0]), "r"(a[mt][1]), "r"(a[mt][2]), "r"(a[mt][3]),
                          "r"(b[nt][0]), "r"(b[nt][1]));
                }
        }

        __syncthreads();

        if (iter + 1 < NKT) {
            uint32_t* ap = A2s + l_row * A_ST + l_half * 4;
            ap[0] = pa.x; ap[1] = pa.y; ap[2] = pa.z; ap[3] = pa.w;
            uint32_t* bp = B2s + l_half * 4 * B_ST + l_row;
            bp[0] = pb.x; bp[B_ST] = pb.y; bp[2 * B_ST] = pb.z; bp[3 * B_ST] = pb.w;
        }
    }

    #pragma unroll
    for (int mt = 0; mt < 4; mt++) {
        int row0 = bm + wm + mt * 16 + gid;
        #pragma unroll
        for (int nt = 0; nt < 4; nt++) {
            int col0 = bn + wn + nt * 8 + tig * 2;
            if (col0 >= DE) continue;
            float b0 = bias[col0], b1 = bias[col0 + 1];
            if (row0 < N_NODES) {
                *(__half2*)(g_proph + (size_t)row0 * DE + col0) =
                    __floats2half2_rn(c[mt][nt][0] + b0, c[mt][nt][1] + b1);
            }
            if (row0 + 8 < N_NODES) {
                *(__half2*)(g_proph + (size_t)(row0 + 8) * DE + col0) =
                    __floats2half2_rn(c[mt][nt][2] + b0, c[mt][nt][3] + b1);
            }
        }
    }
}

// ---------------- counting sort: histogram ----------------
__global__ void hist_kernel(const int* __restrict__ edges) {
    int i = blockIdx.x * blockDim.x + threadIdx.x;
    if (i >= N_EDGES_TOTAL) return;
    atomicAdd(&g_cnt_i[edges[2 * i + 1]], 1);
}

// ---------------- scan pass 1: per-block (1024 counts) sums ----------------
__global__ void scan1_kernel() {
    __shared__ int sh[256];
    int b = blockIdx.x, t = threadIdx.x;
    int base = b * 1024 + t * 4;
    int s = 0;
    #pragma unroll
    for (int j = 0; j < 4; j++) {
        int idx = base + j;
        if (idx < N_NODES) s += g_cnt_i[idx];
    }
    sh[t] = s;
    __syncthreads();
    for (int st = 128; st > 0; st >>= 1) {
        if (t < st) sh[t] += sh[t + st];
        __syncthreads();
    }
    if (t == 0) g_bsum[b] = sh[0];
}

// ---------------- scan pass 2: exclusive scan of block sums ----------------
__global__ void scan2_kernel() {
    if (threadIdx.x == 0) {
        int run = 0;
        for (int i = 0; i < NBLK_SCAN; i++) {
            int v = g_bsum[i];
            g_bsum[i] = run;
            run += v;
        }
    }
}

// ---------------- scan pass 3: per-block exclusive scan -> offsets ----------------
__global__ void scan3_kernel() {
    __shared__ int buf0[256], buf1[256];
    int b = blockIdx.x, t = threadIdx.x;
    int base = b * 1024 + t * 4;
    int c[4];
    int s = 0;
    #pragma unroll
    for (int j = 0; j < 4; j++) {
        int idx = base + j;
        c[j] = (idx < N_NODES) ? g_cnt_i[idx] : 0;
        s += c[j];
    }
    buf0[t] = s;
    __syncthreads();
    // inclusive Hillis-Steele scan over 256 thread sums (ping-pong)
    int* src = buf0; int* dst = buf1;
    for (int st = 1; st < 256; st <<= 1) {
        int v = src[t];
        if (t >= st) v += src[t - st];
        dst[t] = v;
        __syncthreads();
        int* tmp = src; src = dst; dst = tmp;
    }
    int pre = g_bsum[b] + ((t > 0) ? src[t - 1] : 0);   // exclusive prefix
    #pragma unroll
    for (int j = 0; j < 4; j++) {
        int idx = base + j;
        if (idx < N_NODES) {
            g_off[idx] = pre;
            g_cur[idx] = pre;
        }
        pre += c[j];
    }
}

// ---------------- reorder: group edge indices by target ----------------
__global__ void reorder_kernel(const int* __restrict__ edges) {
    int i = blockIdx.x * blockDim.x + threadIdx.x;
    if (i >= N_EDGES_TOTAL) return;
    int tgt = edges[2 * i + 1];
    int pos = atomicAdd(&g_cur[tgt], 1);
    g_sorted[pos] = i;
}

// ---------------- gather-reduce + normalize: one warp per target ----------------
__global__ __launch_bounds__(256)
void gather_kernel(const int* __restrict__ edges,
                   const int* __restrict__ pos_lists,
                   float* __restrict__ out) {
    int w = (int)((blockIdx.x * (size_t)blockDim.x + threadIdx.x) >> 5);
    int lane = threadIdx.x & 31;
    if (w >= N_NODES) return;

    int deg = g_cnt_i[w];
    int off = g_off[w];

    float2 acc0 = make_float2(0.f, 0.f);
    float2 acc1 = make_float2(0.f, 0.f);
    float2 acc2 = make_float2(0.f, 0.f);
    float2 acc3 = make_float2(0.f, 0.f);

    // software pipeline on edge metadata
    int eidx_n = 0, src_n = 0, p_n = 0;
    if (deg > 0) {
        eidx_n = g_sorted[off];
        src_n  = edges[2 * eidx_n];
        p_n    = pos_lists[eidx_n];
    }

    for (int k = 0; k < deg; k++) {
        int eidx = eidx_n, src = src_n, p = p_n;
        if (k + 1 < deg) {
            eidx_n = g_sorted[off + k + 1];
            src_n  = edges[2 * eidx_n];
            p_n    = pos_lists[eidx_n];
        }
        int e = eidx / M_EDGES;
        const __half2* pr = (const __half2*)g_proph + (size_t)src * (DE / 2) + e * (D / 2);
        const float2*  gt = (const float2*)g_gate + (size_t)p * (D / 2);

        float2 a0 = __half22float2(pr[lane]);
        float2 g0 = gt[lane];
        float2 a1 = __half22float2(pr[lane + 32]);
        float2 g1 = gt[lane + 32];
        float2 a2 = __half22float2(pr[lane + 64]);
        float2 g2 = gt[lane + 64];
        acc0.x += a0.x * g0.x; acc0.y += a0.y * g0.y;
        acc1.x += a1.x * g1.x; acc1.y += a1.y * g1.y;
        acc2.x += a2.x * g2.x; acc2.y += a2.y * g2.y;
        if (lane < 5) {
            float2 a3 = __half22float2(pr[lane + 96]);
            float2 g3 = gt[lane + 96];
            acc3.x += a3.x * g3.x; acc3.y += a3.y * g3.y;
        }
    }

    float r = 1.0f / (((deg == 0) ? 1.0f : (float)deg) + 1e-8f);
    float* ob = out + (size_t)w * D;
    *(float2*)(ob + 2 * lane)        = make_float2(acc0.x * r, acc0.y * r);
    *(float2*)(ob + 2 * (lane + 32)) = make_float2(acc1.x * r, acc1.y * r);
    *(float2*)(ob + 2 * (lane + 64)) = make_float2(acc2.x * r, acc2.y * r);
    if (lane < 5)
        *(float2*)(ob + 2 * (lane + 96)) = make_float2(acc3.x * r, acc3.y * r);
}

// ---------------- launch ----------------
extern "C" void kernel_launch(void* const* d_in, const int* in_sizes, int n_in,
                              void* d_out, int out_size) {
    const float* node_states = (const float*)d_in[0];
    const int*   edges       = (const int*)  d_in[1];
    const int*   pos_lists   = (const int*)  d_in[2];
    const float* W_transform = (const float*)d_in[3];
    const float* b_transform = (const float*)d_in[4];
    const float* W_pos       = (const float*)d_in[5];
    const float* b_pos       = (const float*)d_in[6];
    float* out = (float*)d_out;

    zero_cnt_kernel<<<(N_NODES + 255) / 256, 256>>>();
    gating_kernel<<<N_POS, 256>>>(W_pos, b_pos);
    {
        int n = N_NODES * (KP / 2);
        convertA_kernel<<<(n + 255) / 256, 256>>>(node_states);
    }
    {
        int n = DE * (KP / 2);
        convertW_kernel<<<(n + 255) / 256, 256>>>(W_transform);
    }
    hist_kernel<<<(N_EDGES_TOTAL + 255) / 256, 256>>>(edges);
    scan1_kernel<<<NBLK_SCAN, 256>>>();
    scan2_kernel<<<1, 32>>>();
    scan3_kernel<<<NBLK_SCAN, 256>>>();
    reorder_kernel<<<(N_EDGES_TOTAL + 255) / 256, 256>>>(edges);
    {
        dim3 grid((DE + 127) / 128, (N_NODES + 127) / 128);
        gemm_fp16_kernel<<<grid, 256>>>(b_transform);
    }
    {
        int blocks = (N_NODES * 32 + 255) / 256;
        gather_kernel<<<blocks, 256>>>(edges, pos_lists, out);
    }
}

// round 14
// speedup vs baseline: 3.8597x; 1.0340x over previous
#include <cuda_runtime.h>
#include <cuda_fp16.h>
#include <math.h>
#include <stdint.h>

#define N_NODES 100000
#define D 202
#define E_TYPES 6
#define M_EDGES 200000
#define N_POS 512
#define DE (D * E_TYPES)     // 1212
#define N_EDGES_TOTAL (E_TYPES * M_EDGES)
#define KP 224               // K padded to 7 tiles of 32
#define NBLK_SCAN 98         // ceil(100000/1024)

// ---------------- device scratch ----------------
__device__ __align__(16) __half g_proph[(size_t)N_NODES * DE];  // 242 MB fp16 prop
__device__ float g_gate[N_POS * D];
__device__ __align__(16) __half g_Ah[(size_t)N_NODES * KP];
__device__ __align__(16) __half g_Bt[(size_t)DE * KP];
__device__ int g_cnt_i[N_NODES];
__device__ int g_off[N_NODES];
__device__ int g_cur[N_NODES];
__device__ int g_sorted[N_EDGES_TOTAL];
__device__ int g_bsum[NBLK_SCAN];

// ---------------- zero histogram ----------------
__global__ void zero_cnt_kernel() {
    int i = blockIdx.x * blockDim.x + threadIdx.x;
    if (i < N_NODES) g_cnt_i[i] = 0;
}

// ---------------- position gating table ----------------
__global__ void gating_kernel(const float* __restrict__ W_pos,
                              const float* __restrict__ b_pos) {
    __shared__ float emb[D];
    int p = blockIdx.x;
    int t = threadIdx.x;
    if (t < 100) {
        float inv = powf(10000.0f, -(float)t / 100.0f);
        float s = (float)p * inv;
        emb[t]       = sinf(s);
        emb[100 + t] = cosf(s);
    }
    if (t == 100) { emb[200] = 0.0f; emb[201] = 0.0f; }
    __syncthreads();
    for (int c = t; c < D; c += blockDim.x) {
        float acc = b_pos[c];
        #pragma unroll 4
        for (int k = 0; k < 200; k++)
            acc += emb[k] * W_pos[k * D + c];
        g_gate[p * D + c] = 2.0f / (1.0f + expf(-acc));
    }
}

// ---------------- convert A -> fp16, K padded ----------------
__global__ void convertA_kernel(const float* __restrict__ A) {
    int i = blockIdx.x * blockDim.x + threadIdx.x;
    if (i >= N_NODES * (KP / 2)) return;
    int n  = i / (KP / 2);
    int kp = (i - n * (KP / 2)) * 2;
    float v0 = (kp     < D) ? A[(size_t)n * D + kp]     : 0.0f;
    float v1 = (kp + 1 < D) ? A[(size_t)n * D + kp + 1] : 0.0f;
    ((__half2*)g_Ah)[i] = __floats2half2_rn(v0, v1);
}

// ---------------- transpose + convert W -> fp16 [DE, KP] K-major ----------------
__global__ void convertW_kernel(const float* __restrict__ W) {
    int i = blockIdx.x * blockDim.x + threadIdx.x;
    if (i >= DE * (KP / 2)) return;
    int n  = i / (KP / 2);
    int kp = (i - n * (KP / 2)) * 2;
    float v0 = (kp     < D) ? W[(size_t)kp * DE + n]       : 0.0f;
    float v1 = (kp + 1 < D) ? W[(size_t)(kp + 1) * DE + n] : 0.0f;
    ((__half2*)g_Bt)[i] = __floats2half2_rn(v0, v1);
}

// ---------------- FP16 GEMM v3: GBK=32, double-buffered smem ----------------
#define NKT 7                // 224/32
#define A_ST 17              // A2s row stride in words (16 half2 + 1 pad)
#define B_ST 136             // B2s k2-row stride in words
#define A_BUF (128 * A_ST)   // 2176 words per buffer
#define B_BUF (16 * B_ST)    // 2176 words per buffer

__global__ __launch_bounds__(256)
void gemm_fp16_kernel(const float* __restrict__ bias) {
    __shared__ uint32_t A2s[2 * A_BUF];   // 17.4 KB
    __shared__ uint32_t B2s[2 * B_BUF];   // 17.4 KB

    const int tid  = threadIdx.x;
    const int lane = tid & 31;
    const int warp = tid >> 5;
    const int gid  = lane >> 2;
    const int tig  = lane & 3;
    const int wm   = (warp & 1) * 64;
    const int wn   = (warp >> 1) * 32;

    const int bm = blockIdx.y * 128;
    const int bn = blockIdx.x * 128;

    // load mapping: thread t -> row t>>1, quads q0=(t&1)*2, q0+1  (quad = uint4 = 8 halves)
    const int l_row = tid >> 1;
    const int l_q0  = (tid & 1) * 2;

    float c[4][4][4];
    #pragma unroll
    for (int mt = 0; mt < 4; mt++)
        #pragma unroll
        for (int nt = 0; nt < 4; nt++)
            #pragma unroll
            for (int r = 0; r < 4; r++) c[mt][nt][r] = 0.0f;

    uint4 pa[2], pb[2];

    // ---- prefetch tile 0 into regs ----
    {
        int gm = bm + l_row;
        int gn = bn + l_row;
        #pragma unroll
        for (int q = 0; q < 2; q++) {
            pa[q] = make_uint4(0u, 0u, 0u, 0u);
            if (gm < N_NODES)
                pa[q] = *(const uint4*)(g_Ah + (size_t)gm * KP + (l_q0 + q) * 8);
            pb[q] = make_uint4(0u, 0u, 0u, 0u);
            if (gn < DE)
                pb[q] = *(const uint4*)(g_Bt + (size_t)gn * KP + (l_q0 + q) * 8);
        }
    }
    // ---- store tile 0 to buffer 0 ----
    {
        #pragma unroll
        for (int q = 0; q < 2; q++) {
            uint32_t* ap = A2s + l_row * A_ST + (l_q0 + q) * 4;
            ap[0] = pa[q].x; ap[1] = pa[q].y; ap[2] = pa[q].z; ap[3] = pa[q].w;
            uint32_t* bp = B2s + (l_q0 + q) * 4 * B_ST + l_row;
            bp[0] = pb[q].x; bp[B_ST] = pb[q].y;
            bp[2 * B_ST] = pb[q].z; bp[3 * B_ST] = pb[q].w;
        }
    }
    __syncthreads();

    for (int iter = 0; iter < NKT; iter++) {
        const int cur = iter & 1;
        const int nxt = cur ^ 1;

        // ---- prefetch tile iter+1 into regs ----
        if (iter + 1 < NKT) {
            const int kk = (iter + 1) * 32;
            int gm = bm + l_row;
            int gn = bn + l_row;
            #pragma unroll
            for (int q = 0; q < 2; q++) {
                pa[q] = make_uint4(0u, 0u, 0u, 0u);
                if (gm < N_NODES)
                    pa[q] = *(const uint4*)(g_Ah + (size_t)gm * KP + kk + (l_q0 + q) * 8);
                pb[q] = make_uint4(0u, 0u, 0u, 0u);
                if (gn < DE)
                    pb[q] = *(const uint4*)(g_Bt + (size_t)gn * KP + kk + (l_q0 + q) * 8);
            }
        }

        // ---- compute current buffer: 2 k16 steps ----
        {
            const uint32_t* As = A2s + cur * A_BUF;
            const uint32_t* Bs = B2s + cur * B_BUF;
            #pragma unroll
            for (int s = 0; s < 2; s++) {
                const int ko = s * 8;   // k2 offset of this k16 step
                uint32_t a[4][4];
                #pragma unroll
                for (int mt = 0; mt < 4; mt++) {
                    int r0 = wm + mt * 16 + gid;
                    a[mt][0] = As[r0 * A_ST + ko + tig];
                    a[mt][1] = As[(r0 + 8) * A_ST + ko + tig];
                    a[mt][2] = As[r0 * A_ST + ko + tig + 4];
                    a[mt][3] = As[(r0 + 8) * A_ST + ko + tig + 4];
                }
                uint32_t b[4][2];
                #pragma unroll
                for (int nt = 0; nt < 4; nt++) {
                    int cn = wn + nt * 8 + gid;
                    b[nt][0] = Bs[(ko + tig) * B_ST + cn];
                    b[nt][1] = Bs[(ko + tig + 4) * B_ST + cn];
                }
                #pragma unroll
                for (int mt = 0; mt < 4; mt++)
                    #pragma unroll
                    for (int nt = 0; nt < 4; nt++) {
                        asm volatile(
                            "mma.sync.aligned.m16n8k16.row.col.f32.f16.f16.f32 "
                            "{%0,%1,%2,%3}, {%4,%5,%6,%7}, {%8,%9}, {%0,%1,%2,%3};"
                            : "+f"(c[mt][nt][0]), "+f"(c[mt][nt][1]),
                              "+f"(c[mt][nt][2]), "+f"(c[mt][nt][3])
                            : "r"(a[mt][0]), "r"(a[mt][1]), "r"(a[mt][2]), "r"(a[mt][3]),
                              "r"(b[nt][0]), "r"(b[nt][1]));
                    }
            }
        }

        // ---- store prefetched tile to the other buffer ----
        if (iter + 1 < NKT) {
            uint32_t* As = A2s + nxt * A_BUF;
            uint32_t* Bs = B2s + nxt * B_BUF;
            #pragma unroll
            for (int q = 0; q < 2; q++) {
                uint32_t* ap = As + l_row * A_ST + (l_q0 + q) * 4;
                ap[0] = pa[q].x; ap[1] = pa[q].y; ap[2] = pa[q].z; ap[3] = pa[q].w;
                uint32_t* bp = Bs + (l_q0 + q) * 4 * B_ST + l_row;
                bp[0] = pb[q].x; bp[B_ST] = pb[q].y;
                bp[2 * B_ST] = pb[q].z; bp[3 * B_ST] = pb[q].w;
            }
        }
        __syncthreads();
    }

    // ---- epilogue: bias add + fp16 store ----
    #pragma unroll
    for (int mt = 0; mt < 4; mt++) {
        int row0 = bm + wm + mt * 16 + gid;
        #pragma unroll
        for (int nt = 0; nt < 4; nt++) {
            int col0 = bn + wn + nt * 8 + tig * 2;
            if (col0 >= DE) continue;
            float b0 = bias[col0], b1 = bias[col0 + 1];
            if (row0 < N_NODES) {
                *(__half2*)(g_proph + (size_t)row0 * DE + col0) =
                    __floats2half2_rn(c[mt][nt][0] + b0, c[mt][nt][1] + b1);
            }
            if (row0 + 8 < N_NODES) {
                *(__half2*)(g_proph + (size_t)(row0 + 8) * DE + col0) =
                    __floats2half2_rn(c[mt][nt][2] + b0, c[mt][nt][3] + b1);
            }
        }
    }
}

// ---------------- counting sort: histogram ----------------
__global__ void hist_kernel(const int* __restrict__ edges) {
    int i = blockIdx.x * blockDim.x + threadIdx.x;
    if (i >= N_EDGES_TOTAL) return;
    atomicAdd(&g_cnt_i[edges[2 * i + 1]], 1);
}

// ---------------- scan pass 1: per-block (1024 counts) sums ----------------
__global__ void scan1_kernel() {
    __shared__ int sh[256];
    int b = blockIdx.x, t = threadIdx.x;
    int base = b * 1024 + t * 4;
    int s = 0;
    #pragma unroll
    for (int j = 0; j < 4; j++) {
        int idx = base + j;
        if (idx < N_NODES) s += g_cnt_i[idx];
    }
    sh[t] = s;
    __syncthreads();
    for (int st = 128; st > 0; st >>= 1) {
        if (t < st) sh[t] += sh[t + st];
        __syncthreads();
    }
    if (t == 0) g_bsum[b] = sh[0];
}

// ---------------- scan pass 2: parallel exclusive scan of 98 block sums ----------------
__global__ void scan2_kernel() {
    __shared__ int buf0[128], buf1[128];
    int t = threadIdx.x;
    int v = (t < NBLK_SCAN) ? g_bsum[t] : 0;
    buf0[t] = v;
    __syncthreads();
    int* src = buf0; int* dst = buf1;
    for (int st = 1; st < 128; st <<= 1) {
        int x = src[t];
        if (t >= st) x += src[t - st];
        dst[t] = x;
        __syncthreads();
        int* tmp = src; src = dst; dst = tmp;
    }
    if (t < NBLK_SCAN) g_bsum[t] = src[t] - v;   // exclusive
}

// ---------------- scan pass 3: per-block exclusive scan -> offsets ----------------
__global__ void scan3_kernel() {
    __shared__ int buf0[256], buf1[256];
    int b = blockIdx.x, t = threadIdx.x;
    int base = b * 1024 + t * 4;
    int c[4];
    int s = 0;
    #pragma unroll
    for (int j = 0; j < 4; j++) {
        int idx = base + j;
        c[j] = (idx < N_NODES) ? g_cnt_i[idx] : 0;
        s += c[j];
    }
    buf0[t] = s;
    __syncthreads();
    int* src = buf0; int* dst = buf1;
    for (int st = 1; st < 256; st <<= 1) {
        int v = src[t];
        if (t >= st) v += src[t - st];
        dst[t] = v;
        __syncthreads();
        int* tmp = src; src = dst; dst = tmp;
    }
    int pre = g_bsum[b] + ((t > 0) ? src[t - 1] : 0);
    #pragma unroll
    for (int j = 0; j < 4; j++) {
        int idx = base + j;
        if (idx < N_NODES) {
            g_off[idx] = pre;
            g_cur[idx] = pre;
        }
        pre += c[j];
    }
}

// ---------------- reorder: group edge indices by target ----------------
__global__ void reorder_kernel(const int* __restrict__ edges) {
    int i = blockIdx.x * blockDim.x + threadIdx.x;
    if (i >= N_EDGES_TOTAL) return;
    int tgt = edges[2 * i + 1];
    int pos = atomicAdd(&g_cur[tgt], 1);
    g_sorted[pos] = i;
}

// ---------------- gather-reduce + normalize: one warp per target ----------------
__global__ __launch_bounds__(256)
void gather_kernel(const int* __restrict__ edges,
                   const int* __restrict__ pos_lists,
                   float* __restrict__ out) {
    int w = (int)((blockIdx.x * (size_t)blockDim.x + threadIdx.x) >> 5);
    int lane = threadIdx.x & 31;
    if (w >= N_NODES) return;

    int deg = g_cnt_i[w];
    int off = g_off[w];

    float2 acc0 = make_float2(0.f, 0.f);
    float2 acc1 = make_float2(0.f, 0.f);
    float2 acc2 = make_float2(0.f, 0.f);
    float2 acc3 = make_float2(0.f, 0.f);

    int eidx_n = 0, src_n = 0, p_n = 0;
    if (deg > 0) {
        eidx_n = g_sorted[off];
        src_n  = edges[2 * eidx_n];
        p_n    = pos_lists[eidx_n];
    }

    for (int k = 0; k < deg; k++) {
        int eidx = eidx_n, src = src_n, p = p_n;
        if (k + 1 < deg) {
            eidx_n = g_sorted[off + k + 1];
            src_n  = edges[2 * eidx_n];
            p_n    = pos_lists[eidx_n];
        }
        int e = eidx / M_EDGES;
        const __half2* pr = (const __half2*)g_proph + (size_t)src * (DE / 2) + e * (D / 2);
        const float2*  gt = (const float2*)g_gate + (size_t)p * (D / 2);

        float2 a0 = __half22float2(pr[lane]);
        float2 g0 = gt[lane];
        float2 a1 = __half22float2(pr[lane + 32]);
        float2 g1 = gt[lane + 32];
        float2 a2 = __half22float2(pr[lane + 64]);
        float2 g2 = gt[lane + 64];
        acc0.x += a0.x * g0.x; acc0.y += a0.y * g0.y;
        acc1.x += a1.x * g1.x; acc1.y += a1.y * g1.y;
        acc2.x += a2.x * g2.x; acc2.y += a2.y * g2.y;
        if (lane < 5) {
            float2 a3 = __half22float2(pr[lane + 96]);
            float2 g3 = gt[lane + 96];
            acc3.x += a3.x * g3.x; acc3.y += a3.y * g3.y;
        }
    }

    float r = 1.0f / (((deg == 0) ? 1.0f : (float)deg) + 1e-8f);
    float* ob = out + (size_t)w * D;
    *(float2*)(ob + 2 * lane)        = make_float2(acc0.x * r, acc0.y * r);
    *(float2*)(ob + 2 * (lane + 32)) = make_float2(acc1.x * r, acc1.y * r);
    *(float2*)(ob + 2 * (lane + 64)) = make_float2(acc2.x * r, acc2.y * r);
    if (lane < 5)
        *(float2*)(ob + 2 * (lane + 96)) = make_float2(acc3.x * r, acc3.y * r);
}

// ---------------- launch ----------------
extern "C" void kernel_launch(void* const* d_in, const int* in_sizes, int n_in,
                              void* d_out, int out_size) {
    const float* node_states = (const float*)d_in[0];
    const int*   edges       = (const int*)  d_in[1];
    const int*   pos_lists   = (const int*)  d_in[2];
    const float* W_transform = (const float*)d_in[3];
    const float* b_transform = (const float*)d_in[4];
    const float* W_pos       = (const float*)d_in[5];
    const float* b_pos       = (const float*)d_in[6];
    float* out = (float*)d_out;

    zero_cnt_kernel<<<(N_NODES + 255) / 256, 256>>>();
    gating_kernel<<<N_POS, 256>>>(W_pos, b_pos);
    {
        int n = N_NODES * (KP / 2);
        convertA_kernel<<<(n + 255) / 256, 256>>>(node_states);
    }
    {
        int n = DE * (KP / 2);
        convertW_kernel<<<(n + 255) / 256, 256>>>(W_transform);
    }
    hist_kernel<<<(N_EDGES_TOTAL + 255) / 256, 256>>>(edges);
    scan1_kernel<<<NBLK_SCAN, 256>>>();
    scan2_kernel<<<1, 128>>>();
    scan3_kernel<<<NBLK_SCAN, 256>>>();
    reorder_kernel<<<(N_EDGES_TOTAL + 255) / 256, 256>>>(edges);
    {
        dim3 grid((DE + 127) / 128, (N_NODES + 127) / 128);
        gemm_fp16_kernel<<<grid, 256>>>(b_transform);
    }
    {
        int blocks = (N_NODES * 32 + 255) / 256;
        gather_kernel<<<blocks, 256>>>(edges, pos_lists, out);
    }
}

// round 16
// speedup vs baseline: 4.1232x; 1.0683x over previous
#include <cuda_runtime.h>
#include <cuda_fp16.h>
#include <math.h>
#include <stdint.h>

#define N_NODES 100000
#define D 202
#define E_TYPES 6
#define M_EDGES 200000
#define N_POS 512
#define DE (D * E_TYPES)     // 1212
#define N_EDGES_TOTAL (E_TYPES * M_EDGES)
#define KP 224               // K padded to 7 tiles of 32
#define NBLK_SCAN 98         // ceil(100000/1024)

// ---------------- device scratch ----------------
__device__ __align__(16) __half g_proph[(size_t)N_NODES * DE];  // 242 MB fp16 prop
__device__ float g_gate[N_POS * D];
__device__ __align__(16) __half g_Ah[(size_t)N_NODES * KP];
__device__ __align__(16) __half g_Bt[(size_t)DE * KP];
__device__ int g_cnt_i[N_NODES];
__device__ int g_off[N_NODES];
__device__ int g_cur[N_NODES];
__device__ int g_sorted[N_EDGES_TOTAL];
__device__ int g_bsum[NBLK_SCAN];

// ---------------- zero histogram ----------------
__global__ void zero_cnt_kernel() {
    int i = blockIdx.x * blockDim.x + threadIdx.x;
    if (i < N_NODES) g_cnt_i[i] = 0;
}

// ---------------- position gating table ----------------
__global__ void gating_kernel(const float* __restrict__ W_pos,
                              const float* __restrict__ b_pos) {
    __shared__ float emb[D];
    int p = blockIdx.x;
    int t = threadIdx.x;
    if (t < 100) {
        float inv = powf(10000.0f, -(float)t / 100.0f);
        float s = (float)p * inv;
        emb[t]       = sinf(s);
        emb[100 + t] = cosf(s);
    }
    if (t == 100) { emb[200] = 0.0f; emb[201] = 0.0f; }
    __syncthreads();
    for (int c = t; c < D; c += blockDim.x) {
        float acc = b_pos[c];
        #pragma unroll 4
        for (int k = 0; k < 200; k++)
            acc += emb[k] * W_pos[k * D + c];
        g_gate[p * D + c] = 2.0f / (1.0f + expf(-acc));
    }
}

// ---------------- convert A -> fp16, K padded ----------------
__global__ void convertA_kernel(const float* __restrict__ A) {
    int i = blockIdx.x * blockDim.x + threadIdx.x;
    if (i >= N_NODES * (KP / 2)) return;
    int n  = i / (KP / 2);
    int kp = (i - n * (KP / 2)) * 2;
    float v0 = (kp     < D) ? A[(size_t)n * D + kp]     : 0.0f;
    float v1 = (kp + 1 < D) ? A[(size_t)n * D + kp + 1] : 0.0f;
    ((__half2*)g_Ah)[i] = __floats2half2_rn(v0, v1);
}

// ---------------- transpose + convert W -> fp16 [DE, KP] K-major ----------------
__global__ void convertW_kernel(const float* __restrict__ W) {
    int i = blockIdx.x * blockDim.x + threadIdx.x;
    if (i >= DE * (KP / 2)) return;
    int n  = i / (KP / 2);
    int kp = (i - n * (KP / 2)) * 2;
    float v0 = (kp     < D) ? W[(size_t)kp * DE + n]       : 0.0f;
    float v1 = (kp + 1 < D) ? W[(size_t)(kp + 1) * DE + n] : 0.0f;
    ((__half2*)g_Bt)[i] = __floats2half2_rn(v0, v1);
}

// ---------------- FP16 GEMM v4: ldmatrix fragments, GBK=32, double-buffered ----------------
#define NKT 7                // 224/32
#define T_ST 20              // tile row stride in words (16 half2 + 4 pad) — conflict-free
#define T_BUF (128 * T_ST)   // 2560 words per buffer

__global__ __launch_bounds__(256)
void gemm_fp16_kernel(const float* __restrict__ bias) {
    __shared__ uint32_t A2s[2 * T_BUF];   // 20 KB
    __shared__ uint32_t B2s[2 * T_BUF];   // 20 KB (row-major: [n][k2])

    const int tid  = threadIdx.x;
    const int lane = tid & 31;
    const int warp = tid >> 5;
    const int gid  = lane >> 2;
    const int tig  = lane & 3;
    const int wm   = (warp & 1) * 64;
    const int wn   = (warp >> 1) * 32;

    const int bm = blockIdx.y * 128;
    const int bn = blockIdx.x * 128;

    // gmem->smem mapping: thread t -> row t>>1, quads (t&1)*2 + {0,1}
    const int l_row = tid >> 1;
    const int l_q0  = (tid & 1) * 2;

    // ldmatrix per-lane address components (word offsets within a buffer)
    const int a_lrow  = (lane & 7) + ((lane >> 3) & 1) * 8;
    const int a_lword = ((lane >> 4) & 1) * 4;
    const int b_lrow  = (lane & 7) + ((lane >> 4) & 1) * 8;
    const int b_lword = ((lane >> 3) & 1) * 4;

    const uint32_t sbA = (uint32_t)__cvta_generic_to_shared(A2s);
    const uint32_t sbB = (uint32_t)__cvta_generic_to_shared(B2s);

    float c[4][4][4];
    #pragma unroll
    for (int mt = 0; mt < 4; mt++)
        #pragma unroll
        for (int nt = 0; nt < 4; nt++)
            #pragma unroll
            for (int r = 0; r < 4; r++) c[mt][nt][r] = 0.0f;

    uint4 pa[2], pb[2];

    // ---- prefetch tile 0 into regs ----
    {
        int gm = bm + l_row;
        int gn = bn + l_row;
        #pragma unroll
        for (int q = 0; q < 2; q++) {
            pa[q] = make_uint4(0u, 0u, 0u, 0u);
            if (gm < N_NODES)
                pa[q] = *(const uint4*)(g_Ah + (size_t)gm * KP + (l_q0 + q) * 8);
            pb[q] = make_uint4(0u, 0u, 0u, 0u);
            if (gn < DE)
                pb[q] = *(const uint4*)(g_Bt + (size_t)gn * KP + (l_q0 + q) * 8);
        }
    }
    // ---- store tile 0 to buffer 0 ----
    #pragma unroll
    for (int q = 0; q < 2; q++) {
        *(uint4*)(A2s + l_row * T_ST + (l_q0 + q) * 4) = pa[q];
        *(uint4*)(B2s + l_row * T_ST + (l_q0 + q) * 4) = pb[q];
    }
    __syncthreads();

    for (int iter = 0; iter < NKT; iter++) {
        const int cur = iter & 1;
        const int nxt = cur ^ 1;

        // ---- prefetch tile iter+1 into regs ----
        if (iter + 1 < NKT) {
            const int kk = (iter + 1) * 32;
            int gm = bm + l_row;
            int gn = bn + l_row;
            #pragma unroll
            for (int q = 0; q < 2; q++) {
                pa[q] = make_uint4(0u, 0u, 0u, 0u);
                if (gm < N_NODES)
                    pa[q] = *(const uint4*)(g_Ah + (size_t)gm * KP + kk + (l_q0 + q) * 8);
                pb[q] = make_uint4(0u, 0u, 0u, 0u);
                if (gn < DE)
                    pb[q] = *(const uint4*)(g_Bt + (size_t)gn * KP + kk + (l_q0 + q) * 8);
            }
        }

        // ---- compute current buffer: 2 k16 steps, ldmatrix fragments ----
        {
            const uint32_t abase = sbA + (cur * T_BUF) * 4;
            const uint32_t bbase = sbB + (cur * T_BUF) * 4;
            #pragma unroll
            for (int s = 0; s < 2; s++) {
                const int ko = s * 8;   // k2-word offset of this k16 step
                uint32_t a[4][4];
                #pragma unroll
                for (int mt = 0; mt < 4; mt++) {
                    uint32_t addr = abase +
                        ((wm + mt * 16 + a_lrow) * T_ST + a_lword + ko) * 4;
                    asm volatile(
                        "ldmatrix.sync.aligned.m8n8.x4.shared.b16 {%0,%1,%2,%3}, [%4];"
                        : "=r"(a[mt][0]), "=r"(a[mt][1]), "=r"(a[mt][2]), "=r"(a[mt][3])
                        : "r"(addr));
                }
                uint32_t b[4][2];
                #pragma unroll
                for (int pr = 0; pr < 2; pr++) {
                    uint32_t addr = bbase +
                        ((wn + pr * 16 + b_lrow) * T_ST + b_lword + ko) * 4;
                    asm volatile(
                        "ldmatrix.sync.aligned.m8n8.x4.shared.b16 {%0,%1,%2,%3}, [%4];"
                        : "=r"(b[2 * pr][0]), "=r"(b[2 * pr][1]),
                          "=r"(b[2 * pr + 1][0]), "=r"(b[2 * pr + 1][1])
                        : "r"(addr));
                }
                #pragma unroll
                for (int mt = 0; mt < 4; mt++)
                    #pragma unroll
                    for (int nt = 0; nt < 4; nt++) {
                        asm volatile(
                            "mma.sync.aligned.m16n8k16.row.col.f32.f16.f16.f32 "
                            "{%0,%1,%2,%3}, {%4,%5,%6,%7}, {%8,%9}, {%0,%1,%2,%3};"
                            : "+f"(c[mt][nt][0]), "+f"(c[mt][nt][1]),
                              "+f"(c[mt][nt][2]), "+f"(c[mt][nt][3])
                            : "r"(a[mt][0]), "r"(a[mt][1]), "r"(a[mt][2]), "r"(a[mt][3]),
                              "r"(b[nt][0]), "r"(b[nt][1]));
                    }
            }
        }

        // ---- store prefetched tile to the other buffer ----
        if (iter + 1 < NKT) {
            #pragma unroll
            for (int q = 0; q < 2; q++) {
                *(uint4*)(A2s + nxt * T_BUF + l_row * T_ST + (l_q0 + q) * 4) = pa[q];
                *(uint4*)(B2s + nxt * T_BUF + l_row * T_ST + (l_q0 + q) * 4) = pb[q];
            }
        }
        __syncthreads();
    }

    // ---- epilogue: bias add + fp16 store ----
    #pragma unroll
    for (int mt = 0; mt < 4; mt++) {
        int row0 = bm + wm + mt * 16 + gid;
        #pragma unroll
        for (int nt = 0; nt < 4; nt++) {
            int col0 = bn + wn + nt * 8 + tig * 2;
            if (col0 >= DE) continue;
            float b0 = bias[col0], b1 = bias[col0 + 1];
            if (row0 < N_NODES) {
                *(__half2*)(g_proph + (size_t)row0 * DE + col0) =
                    __floats2half2_rn(c[mt][nt][0] + b0, c[mt][nt][1] + b1);
            }
            if (row0 + 8 < N_NODES) {
                *(__half2*)(g_proph + (size_t)(row0 + 8) * DE + col0) =
                    __floats2half2_rn(c[mt][nt][2] + b0, c[mt][nt][3] + b1);
            }
        }
    }
}

// ---------------- counting sort: histogram ----------------
__global__ void hist_kernel(const int* __restrict__ edges) {
    int i = blockIdx.x * blockDim.x + threadIdx.x;
    if (i >= N_EDGES_TOTAL) return;
    atomicAdd(&g_cnt_i[edges[2 * i + 1]], 1);
}

// ---------------- scan pass 1 ----------------
__global__ void scan1_kernel() {
    __shared__ int sh[256];
    int b = blockIdx.x, t = threadIdx.x;
    int base = b * 1024 + t * 4;
    int s = 0;
    #pragma unroll
    for (int j = 0; j < 4; j++) {
        int idx = base + j;
        if (idx < N_NODES) s += g_cnt_i[idx];
    }
    sh[t] = s;
    __syncthreads();
    for (int st = 128; st > 0; st >>= 1) {
        if (t < st) sh[t] += sh[t + st];
        __syncthreads();
    }
    if (t == 0) g_bsum[b] = sh[0];
}

// ---------------- scan pass 2: parallel exclusive scan of block sums ----------------
__global__ void scan2_kernel() {
    __shared__ int buf0[128], buf1[128];
    int t = threadIdx.x;
    int v = (t < NBLK_SCAN) ? g_bsum[t] : 0;
    buf0[t] = v;
    __syncthreads();
    int* src = buf0; int* dst = buf1;
    for (int st = 1; st < 128; st <<= 1) {
        int x = src[t];
        if (t >= st) x += src[t - st];
        dst[t] = x;
        __syncthreads();
        int* tmp = src; src = dst; dst = tmp;
    }
    if (t < NBLK_SCAN) g_bsum[t] = src[t] - v;
}

// ---------------- scan pass 3 ----------------
__global__ void scan3_kernel() {
    __shared__ int buf0[256], buf1[256];
    int b = blockIdx.x, t = threadIdx.x;
    int base = b * 1024 + t * 4;
    int c[4];
    int s = 0;
    #pragma unroll
    for (int j = 0; j < 4; j++) {
        int idx = base + j;
        c[j] = (idx < N_NODES) ? g_cnt_i[idx] : 0;
        s += c[j];
    }
    buf0[t] = s;
    __syncthreads();
    int* src = buf0; int* dst = buf1;
    for (int st = 1; st < 256; st <<= 1) {
        int v = src[t];
        if (t >= st) v += src[t - st];
        dst[t] = v;
        __syncthreads();
        int* tmp = src; src = dst; dst = tmp;
    }
    int pre = g_bsum[b] + ((t > 0) ? src[t - 1] : 0);
    #pragma unroll
    for (int j = 0; j < 4; j++) {
        int idx = base + j;
        if (idx < N_NODES) {
            g_off[idx] = pre;
            g_cur[idx] = pre;
        }
        pre += c[j];
    }
}

// ---------------- reorder ----------------
__global__ void reorder_kernel(const int* __restrict__ edges) {
    int i = blockIdx.x * blockDim.x + threadIdx.x;
    if (i >= N_EDGES_TOTAL) return;
    int tgt = edges[2 * i + 1];
    int pos = atomicAdd(&g_cur[tgt], 1);
    g_sorted[pos] = i;
}

// ---------------- gather-reduce + normalize ----------------
__global__ __launch_bounds__(256)
void gather_kernel(const int* __restrict__ edges,
                   const int* __restrict__ pos_lists,
                   float* __restrict__ out) {
    int w = (int)((blockIdx.x * (size_t)blockDim.x + threadIdx.x) >> 5);
    int lane = threadIdx.x & 31;
    if (w >= N_NODES) return;

    int deg = g_cnt_i[w];
    int off = g_off[w];

    float2 acc0 = make_float2(0.f, 0.f);
    float2 acc1 = make_float2(0.f, 0.f);
    float2 acc2 = make_float2(0.f, 0.f);
    float2 acc3 = make_float2(0.f, 0.f);

    int eidx_n = 0, src_n = 0, p_n = 0;
    if (deg > 0) {
        eidx_n = g_sorted[off];
        src_n  = edges[2 * eidx_n];
        p_n    = pos_lists[eidx_n];
    }

    for (int k = 0; k < deg; k++) {
        int eidx = eidx_n, src = src_n, p = p_n;
        if (k + 1 < deg) {
            eidx_n = g_sorted[off + k + 1];
            src_n  = edges[2 * eidx_n];
            p_n    = pos_lists[eidx_n];
        }
        int e = eidx / M_EDGES;
        const __half2* pr = (const __half2*)g_proph + (size_t)src * (DE / 2) + e * (D / 2);
        const float2*  gt = (const float2*)g_gate + (size_t)p * (D / 2);

        float2 a0 = __half22float2(pr[lane]);
        float2 g0 = gt[lane];
        float2 a1 = __half22float2(pr[lane + 32]);
        float2 g1 = gt[lane + 32];
        float2 a2 = __half22float2(pr[lane + 64]);
        float2 g2 = gt[lane + 64];
        acc0.x += a0.x * g0.x; acc0.y += a0.y * g0.y;
        acc1.x += a1.x * g1.x; acc1.y += a1.y * g1.y;
        acc2.x += a2.x * g2.x; acc2.y += a2.y * g2.y;
        if (lane < 5) {
            float2 a3 = __half22float2(pr[lane + 96]);
            float2 g3 = gt[lane + 96];
            acc3.x += a3.x * g3.x; acc3.y += a3.y * g3.y;
        }
    }

    float r = 1.0f / (((deg == 0) ? 1.0f : (float)deg) + 1e-8f);
    float* ob = out + (size_t)w * D;
    *(float2*)(ob + 2 * lane)        = make_float2(acc0.x * r, acc0.y * r);
    *(float2*)(ob + 2 * (lane + 32)) = make_float2(acc1.x * r, acc1.y * r);
    *(float2*)(ob + 2 * (lane + 64)) = make_float2(acc2.x * r, acc2.y * r);
    if (lane < 5)
        *(float2*)(ob + 2 * (lane + 96)) = make_float2(acc3.x * r, acc3.y * r);
}

// ---------------- launch ----------------
extern "C" void kernel_launch(void* const* d_in, const int* in_sizes, int n_in,
                              void* d_out, int out_size) {
    const float* node_states = (const float*)d_in[0];
    const int*   edges       = (const int*)  d_in[1];
    const int*   pos_lists   = (const int*)  d_in[2];
    const float* W_transform = (const float*)d_in[3];
    const float* b_transform = (const float*)d_in[4];
    const float* W_pos       = (const float*)d_in[5];
    const float* b_pos       = (const float*)d_in[6];
    float* out = (float*)d_out;

    zero_cnt_kernel<<<(N_NODES + 255) / 256, 256>>>();
    gating_kernel<<<N_POS, 256>>>(W_pos, b_pos);
    {
        int n = N_NODES * (KP / 2);
        convertA_kernel<<<(n + 255) / 256, 256>>>(node_states);
    }
    {
        int n = DE * (KP / 2);
        convertW_kernel<<<(n + 255) / 256, 256>>>(W_transform);
    }
    hist_kernel<<<(N_EDGES_TOTAL + 255) / 256, 256>>>(edges);
    scan1_kernel<<<NBLK_SCAN, 256>>>();
    scan2_kernel<<<1, 128>>>();
    scan3_kernel<<<NBLK_SCAN, 256>>>();
    reorder_kernel<<<(N_EDGES_TOTAL + 255) / 256, 256>>>(edges);
    {
        dim3 grid((DE + 127) / 128, (N_NODES + 127) / 128);
        gemm_fp16_kernel<<<grid, 256>>>(b_transform);
    }
    {
        int blocks = (N_NODES * 32 + 255) / 256;
        gather_kernel<<<blocks, 256>>>(edges, pos_lists, out);
    }
}